// round 2
// baseline (speedup 1.0000x reference)
#include <cuda_runtime.h>
#include <math.h>

// ---------------- problem constants ----------------
#define BATCH 2
#define SEQ   2048
#define DMODEL 2048
#define NHEAD 16
#define HDIM  128
#define RQ    1536
#define RKV   512
#define MTOT  (BATCH*SEQ)          // 4096

// ---------------- scratch (allocation-free: __device__ globals) ----------------
__device__ float g_xq[(size_t)MTOT * RQ];          // X @ Wq_down^T
__device__ float g_q [(size_t)MTOT * DMODEL];      // Q  [B*L, H*d]
__device__ float g_c [(size_t)MTOT * RKV];         // latent C
__device__ float g_k [(size_t)BATCH*NHEAD*SEQ*HDIM]; // K [B,H,L,d]
__device__ float g_v [(size_t)BATCH*NHEAD*SEQ*HDIM]; // V [B,H,L,d]
__device__ float g_o [(size_t)MTOT * DMODEL];      // attn out [B,L,H*d]

// ---------------- generic 128x128x16 SGEMM, C = A @ op(B) ----------------
// TRANS_B: B stored [N,K] row-major (weight W, computing A @ W^T)
// else   : B stored [K,N] row-major
// batching: z -> Ab = A + (z/hmod)*sA ; Bb = B + (z%hmod)*sB ; Cb = C + z*sC
template<bool TRANS_B>
__global__ __launch_bounds__(256, 2)
void sgemm_kernel(const float* __restrict__ A, const float* __restrict__ B,
                  float* __restrict__ C, int M, int N, int K,
                  long sA, long sB, long sC, int hmod)
{
    __shared__ float As[16][132];
    __shared__ float Bs[16][132];

    const int z = blockIdx.z;
    const float* Ab = A + (long)(z / hmod) * sA;
    const float* Bb = B + (long)(z % hmod) * sB;
    float* Cb = C + (long)z * sC;

    const int m0 = blockIdx.y * 128;
    const int n0 = blockIdx.x * 128;
    const int tid = threadIdx.x;
    const int tr = tid >> 4, tc = tid & 15;

    float acc[8][8];
    #pragma unroll
    for (int i = 0; i < 8; i++)
        #pragma unroll
        for (int j = 0; j < 8; j++) acc[i][j] = 0.f;

    const int r  = tid >> 2;
    const int c4 = (tid & 3) << 2;

    for (int k0 = 0; k0 < K; k0 += 16) {
        #pragma unroll
        for (int it = 0; it < 2; it++) {
            int row = r + it * 64;
            float4 v = *(const float4*)(Ab + (long)(m0 + row) * K + k0 + c4);
            As[c4+0][row] = v.x; As[c4+1][row] = v.y;
            As[c4+2][row] = v.z; As[c4+3][row] = v.w;
        }
        if (TRANS_B) {
            #pragma unroll
            for (int it = 0; it < 2; it++) {
                int n = r + it * 64;
                float4 v = *(const float4*)(Bb + (long)(n0 + n) * K + k0 + c4);
                Bs[c4+0][n] = v.x; Bs[c4+1][n] = v.y;
                Bs[c4+2][n] = v.z; Bs[c4+3][n] = v.w;
            }
        } else {
            const int kk = tid >> 5;
            const int n4 = (tid & 31) << 2;
            #pragma unroll
            for (int it = 0; it < 2; it++) {
                int k = kk + it * 8;
                *(float4*)&Bs[k][n4] =
                    *(const float4*)(Bb + (long)(k0 + k) * N + n0 + n4);
            }
        }
        __syncthreads();
        #pragma unroll
        for (int k = 0; k < 16; k++) {
            float4 a0 = *(const float4*)&As[k][tr*8];
            float4 a1 = *(const float4*)&As[k][tr*8+4];
            float4 b0 = *(const float4*)&Bs[k][tc*8];
            float4 b1 = *(const float4*)&Bs[k][tc*8+4];
            float av[8] = {a0.x,a0.y,a0.z,a0.w,a1.x,a1.y,a1.z,a1.w};
            float bv[8] = {b0.x,b0.y,b0.z,b0.w,b1.x,b1.y,b1.z,b1.w};
            #pragma unroll
            for (int i = 0; i < 8; i++)
                #pragma unroll
                for (int j = 0; j < 8; j++)
                    acc[i][j] = fmaf(av[i], bv[j], acc[i][j]);
        }
        __syncthreads();
    }
    #pragma unroll
    for (int i = 0; i < 8; i++) {
        long row = m0 + tr*8 + i;
        float* cp = Cb + row * N + n0 + tc*8;
        *(float4*)cp     = make_float4(acc[i][0],acc[i][1],acc[i][2],acc[i][3]);
        *(float4*)(cp+4) = make_float4(acc[i][4],acc[i][5],acc[i][6],acc[i][7]);
    }
}

// ---------------- fused causal flash attention with ALiBi ----------------
// grid: (L/64 query tiles, B*H). 256 threads. Each thread: 4 rows x (4 score cols / 8 out cols).
// smem: Qs[64][132] | KVs[64][132] (K then reused for V) | Ps[64][68]
#define FLASH_SMEM_FLOATS (64*132 + 64*132 + 64*68)
#define FLASH_SMEM_BYTES  (FLASH_SMEM_FLOATS * 4)

__global__ __launch_bounds__(256, 2)
void flash_kernel(const float* __restrict__ Q, const float* __restrict__ Kg,
                  const float* __restrict__ Vg, float* __restrict__ O)
{
    extern __shared__ float smem[];
    float* Qs  = smem;                 // [64][132]
    float* KVs = smem + 64*132;        // [64][132]
    float* Ps  = smem + 2*64*132;      // [64][68]

    const int bh = blockIdx.y;
    const int b  = bh >> 4, h = bh & 15;
    const int qt = blockIdx.x;
    const int tid = threadIdx.x;
    const int tr = tid >> 4, tc = tid & 15;
    const int q0 = qt * 64;

    const float slope = exp2f(-0.5f * (float)(h + 1)); // ALiBi: base^(h+1), base=2^-0.5
    const float scale = 0.08838834764831843f;          // 1/sqrt(128)

    const float* Qbase = Q  + ((long)(b*SEQ + q0)) * DMODEL + h*HDIM;
    const float* Kbase = Kg + ((long)(b*NHEAD + h)) * SEQ * HDIM;
    const float* Vbase = Vg + ((long)(b*NHEAD + h)) * SEQ * HDIM;

    #pragma unroll
    for (int t = 0; t < 8; t++) {
        int idx = tid + t*256;
        int row = idx >> 5, cc = (idx & 31) << 2;
        *(float4*)&Qs[row*132 + cc] = *(const float4*)(Qbase + (long)row*DMODEL + cc);
    }

    float m_i[4], l_i[4], acc[4][8];
    #pragma unroll
    for (int i = 0; i < 4; i++) {
        m_i[i] = -INFINITY; l_i[i] = 0.f;
        #pragma unroll
        for (int j = 0; j < 8; j++) acc[i][j] = 0.f;
    }

    for (int kt = 0; kt <= qt; kt++) {
        const int k0 = kt * 64;
        __syncthreads();   // prior PV reads of KVs/Ps complete
        #pragma unroll
        for (int t = 0; t < 8; t++) {
            int idx = tid + t*256;
            int row = idx >> 5, cc = (idx & 31) << 2;
            *(float4*)&KVs[row*132 + cc] = *(const float4*)(Kbase + (long)(k0+row)*HDIM + cc);
        }
        __syncthreads();

        // S[4tr+i][4tc+j] = Qrow . Krow
        float s[4][4];
        #pragma unroll
        for (int i = 0; i < 4; i++)
            #pragma unroll
            for (int j = 0; j < 4; j++) s[i][j] = 0.f;
        #pragma unroll 8
        for (int k = 0; k < 128; k += 4) {
            float4 a[4], bb[4];
            #pragma unroll
            for (int i = 0; i < 4; i++) a[i]  = *(const float4*)&Qs [(4*tr+i)*132 + k];
            #pragma unroll
            for (int j = 0; j < 4; j++) bb[j] = *(const float4*)&KVs[(4*tc+j)*132 + k];
            #pragma unroll
            for (int i = 0; i < 4; i++)
                #pragma unroll
                for (int j = 0; j < 4; j++) {
                    s[i][j] = fmaf(a[i].x, bb[j].x, s[i][j]);
                    s[i][j] = fmaf(a[i].y, bb[j].y, s[i][j]);
                    s[i][j] = fmaf(a[i].z, bb[j].z, s[i][j]);
                    s[i][j] = fmaf(a[i].w, bb[j].w, s[i][j]);
                }
        }

        // scale + ALiBi + causal mask, online softmax (row group = 16 lanes, same warp half)
        #pragma unroll
        for (int i = 0; i < 4; i++) {
            const int qi = q0 + 4*tr + i;
            float rv = -INFINITY;
            #pragma unroll
            for (int j = 0; j < 4; j++) {
                const int kj = k0 + 4*tc + j;
                s[i][j] = (kj <= qi) ? fmaf(s[i][j], scale, -slope * (float)(qi - kj))
                                     : -INFINITY;
                rv = fmaxf(rv, s[i][j]);
            }
            #pragma unroll
            for (int off = 8; off; off >>= 1)
                rv = fmaxf(rv, __shfl_xor_sync(0xffffffffu, rv, off));
            const float mnew = fmaxf(m_i[i], rv);
            const float alpha = expf(m_i[i] - mnew);
            m_i[i] = mnew;
            float rs = 0.f;
            float p[4];
            #pragma unroll
            for (int j = 0; j < 4; j++) { p[j] = expf(s[i][j] - mnew); rs += p[j]; }
            #pragma unroll
            for (int off = 8; off; off >>= 1)
                rs += __shfl_xor_sync(0xffffffffu, rs, off);
            l_i[i] = l_i[i] * alpha + rs;
            #pragma unroll
            for (int j = 0; j < 8; j++) acc[i][j] *= alpha;
            #pragma unroll
            for (int j = 0; j < 4; j++) Ps[(4*tr+i)*68 + 4*tc + j] = p[j];
        }
        __syncthreads();  // K reads done, Ps visible

        // load V over the K buffer
        #pragma unroll
        for (int t = 0; t < 8; t++) {
            int idx = tid + t*256;
            int row = idx >> 5, cc = (idx & 31) << 2;
            *(float4*)&KVs[row*132 + cc] = *(const float4*)(Vbase + (long)(k0+row)*HDIM + cc);
        }
        __syncthreads();

        // acc += P @ V   (thread cols = tc*8 .. tc*8+7)
        #pragma unroll 4
        for (int k = 0; k < 64; k++) {
            float pk[4];
            #pragma unroll
            for (int i = 0; i < 4; i++) pk[i] = Ps[(4*tr+i)*68 + k];
            float4 v0 = *(const float4*)&KVs[k*132 + tc*8];
            float4 v1 = *(const float4*)&KVs[k*132 + tc*8 + 4];
            #pragma unroll
            for (int i = 0; i < 4; i++) {
                acc[i][0] = fmaf(pk[i], v0.x, acc[i][0]);
                acc[i][1] = fmaf(pk[i], v0.y, acc[i][1]);
                acc[i][2] = fmaf(pk[i], v0.z, acc[i][2]);
                acc[i][3] = fmaf(pk[i], v0.w, acc[i][3]);
                acc[i][4] = fmaf(pk[i], v1.x, acc[i][4]);
                acc[i][5] = fmaf(pk[i], v1.y, acc[i][5]);
                acc[i][6] = fmaf(pk[i], v1.z, acc[i][6]);
                acc[i][7] = fmaf(pk[i], v1.w, acc[i][7]);
            }
        }
    }

    // normalize + write O[b, q, h*128 + col]
    #pragma unroll
    for (int i = 0; i < 4; i++) {
        const float inv = 1.f / l_i[i];
        long row = (long)(b*SEQ + q0 + 4*tr + i);
        float* op = O + row * DMODEL + h*HDIM + tc*8;
        *(float4*)op     = make_float4(acc[i][0]*inv, acc[i][1]*inv, acc[i][2]*inv, acc[i][3]*inv);
        *(float4*)(op+4) = make_float4(acc[i][4]*inv, acc[i][5]*inv, acc[i][6]*inv, acc[i][7]*inv);
    }
}

// ---------------- launch ----------------
extern "C" void kernel_launch(void* const* d_in, const int* in_sizes, int n_in,
                              void* d_out, int out_size)
{
    const float* X        = (const float*)d_in[0];
    const float* Wq_down  = (const float*)d_in[1];   // [1536, 2048]
    const float* Wq_up    = (const float*)d_in[2];   // [2048, 1536]
    const float* Wkv_down = (const float*)d_in[3];   // [512, 2048]
    const float* k_up     = (const float*)d_in[4];   // [16, 512, 128]
    const float* v_up     = (const float*)d_in[5];   // [16, 512, 128]
    const float* Wo       = (const float*)d_in[6];   // [2048, 2048]
    float* out = (float*)d_out;

    float *xq, *q, *c, *kb, *vb, *ob;
    cudaGetSymbolAddress((void**)&xq, g_xq);
    cudaGetSymbolAddress((void**)&q,  g_q);
    cudaGetSymbolAddress((void**)&c,  g_c);
    cudaGetSymbolAddress((void**)&kb, g_k);
    cudaGetSymbolAddress((void**)&vb, g_v);
    cudaGetSymbolAddress((void**)&ob, g_o);

    cudaFuncSetAttribute(flash_kernel,
                         cudaFuncAttributeMaxDynamicSharedMemorySize, FLASH_SMEM_BYTES);

    dim3 blk(256);

    // 1) Xq = X @ Wq_down^T : [4096,1536]
    sgemm_kernel<true><<<dim3(RQ/128, MTOT/128, 1), blk>>>(
        X, Wq_down, xq, MTOT, RQ, DMODEL, 0, 0, 0, 1);
    // 2) Q = Xq @ Wq_up^T : [4096,2048]
    sgemm_kernel<true><<<dim3(DMODEL/128, MTOT/128, 1), blk>>>(
        xq, Wq_up, q, MTOT, DMODEL, RQ, 0, 0, 0, 1);
    // 3) C = X @ Wkv_down^T : [4096,512]
    sgemm_kernel<true><<<dim3(RKV/128, MTOT/128, 1), blk>>>(
        X, Wkv_down, c, MTOT, RKV, DMODEL, 0, 0, 0, 1);
    // 4) K[b,h] = C_b @ k_up[h] : batched 32x [2048,128]
    sgemm_kernel<false><<<dim3(1, SEQ/128, BATCH*NHEAD), blk>>>(
        c, k_up, kb, SEQ, HDIM, RKV,
        (long)SEQ*RKV, (long)RKV*HDIM, (long)SEQ*HDIM, NHEAD);
    // 5) V likewise
    sgemm_kernel<false><<<dim3(1, SEQ/128, BATCH*NHEAD), blk>>>(
        c, v_up, vb, SEQ, HDIM, RKV,
        (long)SEQ*RKV, (long)RKV*HDIM, (long)SEQ*HDIM, NHEAD);
    // 6) fused causal+ALiBi flash attention -> ob [B,L,H*d]
    flash_kernel<<<dim3(SEQ/64, BATCH*NHEAD), blk, FLASH_SMEM_BYTES>>>(q, kb, vb, ob);
    // 7) out = ob @ Wo^T : [4096,2048]
    sgemm_kernel<true><<<dim3(DMODEL/128, MTOT/128, 1), blk>>>(
        ob, Wo, out, MTOT, DMODEL, DMODEL, 0, 0, 0, 1);
}

// round 4
// speedup vs baseline: 1.5632x; 1.5632x over previous
#include <cuda_runtime.h>
#include <cstdint>
#include <math.h>

// ---------------- problem constants ----------------
#define BATCH 2
#define SEQ   2048
#define DMODEL 2048
#define NHEAD 16
#define HDIM  128
#define RQ    1536
#define RKV   512
#define MTOT  (BATCH*SEQ)          // 4096

// ---------------- scratch (allocation-free: __device__ globals) ----------------
__device__ float g_xq[(size_t)MTOT * RQ];            // X @ Wq_down^T
__device__ float g_q [(size_t)MTOT * DMODEL];        // Q  [B*L, H*d]
__device__ float g_c [(size_t)MTOT * RKV];           // latent C
__device__ float g_k [(size_t)BATCH*NHEAD*SEQ*HDIM]; // K [B,H,L,d]
__device__ float g_v [(size_t)BATCH*NHEAD*SEQ*HDIM]; // V [B,H,L,d]
__device__ float g_o [(size_t)MTOT * DMODEL];        // attn out [B,L,H*d]
__device__ float g_kuT[(size_t)NHEAD*HDIM*RKV];      // k_up transposed: [H, d, r]
__device__ float g_vuT[(size_t)NHEAD*HDIM*RKV];      // v_up transposed

// ---------------- helpers ----------------
__device__ __forceinline__ uint32_t f2tf32(float x) {
    uint32_t r;
    asm("cvt.rna.tf32.f32 %0, %1;" : "=r"(r) : "f"(x));
    return r;
}

// mma.sync m16n8k8 tf32: D = A(16x8 row) * B(8x8 col) + C, fp32 accum.
__device__ __forceinline__ void mma_tf32(float& c0, float& c1, float& c2, float& c3,
                                         uint32_t a0, uint32_t a1, uint32_t a2, uint32_t a3,
                                         uint32_t b0, uint32_t b1) {
    asm volatile(
        "mma.sync.aligned.m16n8k8.row.col.f32.tf32.tf32.f32 "
        "{%0,%1,%2,%3}, {%4,%5,%6,%7}, {%8,%9}, {%0,%1,%2,%3};"
        : "+f"(c0), "+f"(c1), "+f"(c2), "+f"(c3)
        : "r"(a0), "r"(a1), "r"(a2), "r"(a3), "r"(b0), "r"(b1));
}

// ---------------- tf32 tensor-core GEMM: C = A @ B^T ----------------
// A [M,K] row-major, B [N,K] row-major. M%128==0, N%128==0, K%32==0.
// batching: z -> Ab = A + (z/hmod)*sA ; Bb = B + (z%hmod)*sB ; Cb = C + z*sC
// CTA 128x128, BK=32, 8 warps, warp tile 64x32 (4x4 of m16n8k8).
#define BK 32
#define LDS_STRIDE 36   // 32 + 4 pad words: fragment LDS conflict-free, v4-store aligned

__global__ __launch_bounds__(256)
void gemm_tc(const float* __restrict__ A, const float* __restrict__ B,
             float* __restrict__ C, int M, int N, int K,
             long sA, long sB, long sC, int hmod)
{
    __shared__ uint32_t As[128 * LDS_STRIDE];
    __shared__ uint32_t Bs[128 * LDS_STRIDE];

    const int tid = threadIdx.x;
    const int wid = tid >> 5, lane = tid & 31;
    const int g = lane >> 2, t = lane & 3;           // groupID / threadID_in_group
    const int z = blockIdx.z;
    const float* Ab = A + (long)(z / hmod) * sA;
    const float* Bb = B + (long)(z % hmod) * sB;
    float* Cb = C + (long)z * sC;
    const int m0 = blockIdx.y * 128;
    const int n0 = blockIdx.x * 128;

    const int wm = (wid & 1) * 64;                   // warp tile origin in M
    const int wn = (wid >> 1) * 32;                  // warp tile origin in N

    float acc[4][4][4];
    #pragma unroll
    for (int m = 0; m < 4; m++)
        #pragma unroll
        for (int n = 0; n < 4; n++)
            #pragma unroll
            for (int r = 0; r < 4; r++) acc[m][n][r] = 0.f;

    // global-load mapping: 4 passes, each 256 threads cover 32 rows x 8 float4
    const int lrow = tid >> 3;          // 0..31
    const int lc4  = (tid & 7) << 2;    // 0,4,..,28

    for (int k0 = 0; k0 < K; k0 += BK) {
        #pragma unroll
        for (int p = 0; p < 4; p++) {
            int row = lrow + p * 32;
            float4 va = *(const float4*)(Ab + (long)(m0 + row) * K + k0 + lc4);
            uint32_t* dst = &As[row * LDS_STRIDE + lc4];
            dst[0] = f2tf32(va.x); dst[1] = f2tf32(va.y);
            dst[2] = f2tf32(va.z); dst[3] = f2tf32(va.w);
            float4 vb = *(const float4*)(Bb + (long)(n0 + row) * K + k0 + lc4);
            uint32_t* dstb = &Bs[row * LDS_STRIDE + lc4];
            dstb[0] = f2tf32(vb.x); dstb[1] = f2tf32(vb.y);
            dstb[2] = f2tf32(vb.z); dstb[3] = f2tf32(vb.w);
        }
        __syncthreads();

        #pragma unroll
        for (int ks = 0; ks < BK / 8; ks++) {
            const int kk = ks * 8;
            uint32_t af[4][4], bf[4][2];
            #pragma unroll
            for (int m = 0; m < 4; m++) {
                const int r0 = (wm + m * 16 + g) * LDS_STRIDE + kk;
                const int r1 = (wm + m * 16 + g + 8) * LDS_STRIDE + kk;
                af[m][0] = As[r0 + t];
                af[m][1] = As[r1 + t];
                af[m][2] = As[r0 + t + 4];
                af[m][3] = As[r1 + t + 4];
            }
            #pragma unroll
            for (int n = 0; n < 4; n++) {
                const int rn = (wn + n * 8 + g) * LDS_STRIDE + kk;
                bf[n][0] = Bs[rn + t];
                bf[n][1] = Bs[rn + t + 4];
            }
            #pragma unroll
            for (int m = 0; m < 4; m++)
                #pragma unroll
                for (int n = 0; n < 4; n++)
                    mma_tf32(acc[m][n][0], acc[m][n][1], acc[m][n][2], acc[m][n][3],
                             af[m][0], af[m][1], af[m][2], af[m][3],
                             bf[n][0], bf[n][1]);
        }
        __syncthreads();
    }

    // epilogue: c0,c1 -> (row g, cols 2t,2t+1); c2,c3 -> (row g+8)
    #pragma unroll
    for (int m = 0; m < 4; m++) {
        const long row0 = m0 + wm + m * 16 + g;
        #pragma unroll
        for (int n = 0; n < 4; n++) {
            const int col = n0 + wn + n * 8 + 2 * t;
            *(float2*)(Cb + row0 * N + col)       = make_float2(acc[m][n][0], acc[m][n][1]);
            *(float2*)(Cb + (row0 + 8) * N + col) = make_float2(acc[m][n][2], acc[m][n][3]);
        }
    }
}

// ---------------- transpose [H, RKV, HDIM] -> [H, HDIM, RKV] ----------------
__global__ __launch_bounds__(256)
void transpose_up(const float* __restrict__ in, float* __restrict__ out)
{
    __shared__ float t[32][33];
    const int h = blockIdx.z;
    const int r0 = blockIdx.y * 32;   // RKV dim
    const int c0 = blockIdx.x * 32;   // HDIM dim
    const int tx = threadIdx.x & 31, ty0 = threadIdx.x >> 5;
    const float* ip = in + (long)h * RKV * HDIM;
    float* op = out + (long)h * RKV * HDIM;
    #pragma unroll
    for (int r = 0; r < 4; r++) {
        int ty = ty0 + r * 8;
        t[ty][tx] = ip[(long)(r0 + ty) * HDIM + c0 + tx];
    }
    __syncthreads();
    #pragma unroll
    for (int r = 0; r < 4; r++) {
        int ty = ty0 + r * 8;
        op[(long)(c0 + ty) * RKV + r0 + tx] = t[tx][ty];
    }
}

// ---------------- fused causal flash attention with ALiBi (fp32 SIMT) ----------------
#define FLASH_SMEM_FLOATS (64*132 + 64*132 + 64*68)
#define FLASH_SMEM_BYTES  (FLASH_SMEM_FLOATS * 4)

__global__ __launch_bounds__(256, 2)
void flash_kernel(const float* __restrict__ Q, const float* __restrict__ Kg,
                  const float* __restrict__ Vg, float* __restrict__ O)
{
    extern __shared__ float smemf[];
    float* Qs  = smemf;
    float* KVs = smemf + 64*132;
    float* Ps  = smemf + 2*64*132;

    const int bh = blockIdx.y;
    const int b  = bh >> 4, h = bh & 15;
    const int qt = blockIdx.x;
    const int tid = threadIdx.x;
    const int tr = tid >> 4, tc = tid & 15;
    const int q0 = qt * 64;

    const float slope = exp2f(-0.5f * (float)(h + 1));
    const float scale = 0.08838834764831843f;

    const float* Qbase = Q  + ((long)(b*SEQ + q0)) * DMODEL + h*HDIM;
    const float* Kbase = Kg + ((long)(b*NHEAD + h)) * SEQ * HDIM;
    const float* Vbase = Vg + ((long)(b*NHEAD + h)) * SEQ * HDIM;

    #pragma unroll
    for (int t = 0; t < 8; t++) {
        int idx = tid + t*256;
        int row = idx >> 5, cc = (idx & 31) << 2;
        *(float4*)&Qs[row*132 + cc] = *(const float4*)(Qbase + (long)row*DMODEL + cc);
    }

    float m_i[4], l_i[4], acc[4][8];
    #pragma unroll
    for (int i = 0; i < 4; i++) {
        m_i[i] = -INFINITY; l_i[i] = 0.f;
        #pragma unroll
        for (int j = 0; j < 8; j++) acc[i][j] = 0.f;
    }

    for (int kt = 0; kt <= qt; kt++) {
        const int k0 = kt * 64;
        __syncthreads();
        #pragma unroll
        for (int t = 0; t < 8; t++) {
            int idx = tid + t*256;
            int row = idx >> 5, cc = (idx & 31) << 2;
            *(float4*)&KVs[row*132 + cc] = *(const float4*)(Kbase + (long)(k0+row)*HDIM + cc);
        }
        __syncthreads();

        float s[4][4];
        #pragma unroll
        for (int i = 0; i < 4; i++)
            #pragma unroll
            for (int j = 0; j < 4; j++) s[i][j] = 0.f;
        #pragma unroll 8
        for (int k = 0; k < 128; k += 4) {
            float4 a[4], bb[4];
            #pragma unroll
            for (int i = 0; i < 4; i++) a[i]  = *(const float4*)&Qs [(4*tr+i)*132 + k];
            #pragma unroll
            for (int j = 0; j < 4; j++) bb[j] = *(const float4*)&KVs[(4*tc+j)*132 + k];
            #pragma unroll
            for (int i = 0; i < 4; i++)
                #pragma unroll
                for (int j = 0; j < 4; j++) {
                    s[i][j] = fmaf(a[i].x, bb[j].x, s[i][j]);
                    s[i][j] = fmaf(a[i].y, bb[j].y, s[i][j]);
                    s[i][j] = fmaf(a[i].z, bb[j].z, s[i][j]);
                    s[i][j] = fmaf(a[i].w, bb[j].w, s[i][j]);
                }
        }

        #pragma unroll
        for (int i = 0; i < 4; i++) {
            const int qi = q0 + 4*tr + i;
            float rv = -INFINITY;
            #pragma unroll
            for (int j = 0; j < 4; j++) {
                const int kj = k0 + 4*tc + j;
                s[i][j] = (kj <= qi) ? fmaf(s[i][j], scale, -slope * (float)(qi - kj))
                                     : -INFINITY;
                rv = fmaxf(rv, s[i][j]);
            }
            #pragma unroll
            for (int off = 8; off; off >>= 1)
                rv = fmaxf(rv, __shfl_xor_sync(0xffffffffu, rv, off));
            const float mnew = fmaxf(m_i[i], rv);
            const float alpha = expf(m_i[i] - mnew);
            m_i[i] = mnew;
            float rs = 0.f;
            float p[4];
            #pragma unroll
            for (int j = 0; j < 4; j++) { p[j] = expf(s[i][j] - mnew); rs += p[j]; }
            #pragma unroll
            for (int off = 8; off; off >>= 1)
                rs += __shfl_xor_sync(0xffffffffu, rs, off);
            l_i[i] = l_i[i] * alpha + rs;
            #pragma unroll
            for (int j = 0; j < 8; j++) acc[i][j] *= alpha;
            #pragma unroll
            for (int j = 0; j < 4; j++) Ps[(4*tr+i)*68 + 4*tc + j] = p[j];
        }
        __syncthreads();

        #pragma unroll
        for (int t = 0; t < 8; t++) {
            int idx = tid + t*256;
            int row = idx >> 5, cc = (idx & 31) << 2;
            *(float4*)&KVs[row*132 + cc] = *(const float4*)(Vbase + (long)(k0+row)*HDIM + cc);
        }
        __syncthreads();

        #pragma unroll 4
        for (int k = 0; k < 64; k++) {
            float pk[4];
            #pragma unroll
            for (int i = 0; i < 4; i++) pk[i] = Ps[(4*tr+i)*68 + k];
            float4 v0 = *(const float4*)&KVs[k*132 + tc*8];
            float4 v1 = *(const float4*)&KVs[k*132 + tc*8 + 4];
            #pragma unroll
            for (int i = 0; i < 4; i++) {
                acc[i][0] = fmaf(pk[i], v0.x, acc[i][0]);
                acc[i][1] = fmaf(pk[i], v0.y, acc[i][1]);
                acc[i][2] = fmaf(pk[i], v0.z, acc[i][2]);
                acc[i][3] = fmaf(pk[i], v0.w, acc[i][3]);
                acc[i][4] = fmaf(pk[i], v1.x, acc[i][4]);
                acc[i][5] = fmaf(pk[i], v1.y, acc[i][5]);
                acc[i][6] = fmaf(pk[i], v1.z, acc[i][6]);
                acc[i][7] = fmaf(pk[i], v1.w, acc[i][7]);
            }
        }
    }

    #pragma unroll
    for (int i = 0; i < 4; i++) {
        const float inv = 1.f / l_i[i];
        long row = (long)(b*SEQ + q0 + 4*tr + i);
        float* op = O + row * DMODEL + h*HDIM + tc*8;
        *(float4*)op     = make_float4(acc[i][0]*inv, acc[i][1]*inv, acc[i][2]*inv, acc[i][3]*inv);
        *(float4*)(op+4) = make_float4(acc[i][4]*inv, acc[i][5]*inv, acc[i][6]*inv, acc[i][7]*inv);
    }
}

// ---------------- launch ----------------
extern "C" void kernel_launch(void* const* d_in, const int* in_sizes, int n_in,
                              void* d_out, int out_size)
{
    const float* X        = (const float*)d_in[0];
    const float* Wq_down  = (const float*)d_in[1];   // [1536, 2048]
    const float* Wq_up    = (const float*)d_in[2];   // [2048, 1536]
    const float* Wkv_down = (const float*)d_in[3];   // [512, 2048]
    const float* k_up     = (const float*)d_in[4];   // [16, 512, 128]
    const float* v_up     = (const float*)d_in[5];   // [16, 512, 128]
    const float* Wo       = (const float*)d_in[6];   // [2048, 2048]
    float* out = (float*)d_out;

    float *xq, *q, *c, *kb, *vb, *ob, *kuT, *vuT;
    cudaGetSymbolAddress((void**)&xq,  g_xq);
    cudaGetSymbolAddress((void**)&q,   g_q);
    cudaGetSymbolAddress((void**)&c,   g_c);
    cudaGetSymbolAddress((void**)&kb,  g_k);
    cudaGetSymbolAddress((void**)&vb,  g_v);
    cudaGetSymbolAddress((void**)&ob,  g_o);
    cudaGetSymbolAddress((void**)&kuT, g_kuT);
    cudaGetSymbolAddress((void**)&vuT, g_vuT);

    cudaFuncSetAttribute(flash_kernel,
                         cudaFuncAttributeMaxDynamicSharedMemorySize, FLASH_SMEM_BYTES);

    dim3 blk(256);

    // 0) transpose k_up/v_up -> [H, HDIM, RKV] so all GEMMs consume K-major B
    transpose_up<<<dim3(HDIM/32, RKV/32, NHEAD), blk>>>(k_up, kuT);
    transpose_up<<<dim3(HDIM/32, RKV/32, NHEAD), blk>>>(v_up, vuT);

    // 1) Xq = X @ Wq_down^T : [4096,1536]
    gemm_tc<<<dim3(RQ/128, MTOT/128, 1), blk>>>(
        X, Wq_down, xq, MTOT, RQ, DMODEL, 0, 0, 0, 1);
    // 2) Q = Xq @ Wq_up^T : [4096,2048]
    gemm_tc<<<dim3(DMODEL/128, MTOT/128, 1), blk>>>(
        xq, Wq_up, q, MTOT, DMODEL, RQ, 0, 0, 0, 1);
    // 3) C = X @ Wkv_down^T : [4096,512]
    gemm_tc<<<dim3(RKV/128, MTOT/128, 1), blk>>>(
        X, Wkv_down, c, MTOT, RKV, DMODEL, 0, 0, 0, 1);
    // 4) K[b,h] = C_b @ kuT[h]^T : batched 32x [2048,128]
    gemm_tc<<<dim3(1, SEQ/128, BATCH*NHEAD), blk>>>(
        c, kuT, kb, SEQ, HDIM, RKV,
        (long)SEQ*RKV, (long)HDIM*RKV, (long)SEQ*HDIM, NHEAD);
    // 5) V likewise
    gemm_tc<<<dim3(1, SEQ/128, BATCH*NHEAD), blk>>>(
        c, vuT, vb, SEQ, HDIM, RKV,
        (long)SEQ*RKV, (long)HDIM*RKV, (long)SEQ*HDIM, NHEAD);
    // 6) fused causal+ALiBi flash attention -> ob [B,L,H*d]
    flash_kernel<<<dim3(SEQ/64, BATCH*NHEAD), blk, FLASH_SMEM_BYTES>>>(q, kb, vb, ob);
    // 7) out = ob @ Wo^T : [4096,2048]
    gemm_tc<<<dim3(DMODEL/128, MTOT/128, 1), blk>>>(
        ob, Wo, out, MTOT, DMODEL, DMODEL, 0, 0, 0, 1);
}

// round 6
// speedup vs baseline: 3.3781x; 2.1611x over previous
#include <cuda_runtime.h>
#include <cstdint>
#include <math.h>

// ---------------- problem constants ----------------
#define BATCH 2
#define SEQ   2048
#define DMODEL 2048
#define NHEAD 16
#define HDIM  128
#define RQ    1536
#define RKV   512
#define MTOT  (BATCH*SEQ)          // 4096

// ---------------- scratch (allocation-free: __device__ globals) ----------------
__device__ float g_xq[(size_t)MTOT * RQ];            // X @ Wq_down^T
__device__ float g_q [(size_t)MTOT * DMODEL];        // Q  [B*L, H*d]
__device__ float g_c [(size_t)MTOT * RKV];           // latent C
__device__ float g_k [(size_t)BATCH*NHEAD*SEQ*HDIM]; // K [B,H,L,d]
__device__ float g_v [(size_t)BATCH*NHEAD*SEQ*HDIM]; // V [B,H,L,d]
__device__ float g_o [(size_t)MTOT * DMODEL];        // attn out [B,L,H*d]
__device__ float g_kuT[(size_t)NHEAD*HDIM*RKV];      // k_up transposed: [H, d, r]
__device__ float g_vuT[(size_t)NHEAD*HDIM*RKV];      // v_up transposed

// ---------------- helpers ----------------
__device__ __forceinline__ uint32_t f2tf32(float x) {
    uint32_t r;
    asm("cvt.rna.tf32.f32 %0, %1;" : "=r"(r) : "f"(x));
    return r;
}

// mma.sync m16n8k8 tf32: D = A(16x8 row) * B(8x8 col) + C, fp32 accum.
__device__ __forceinline__ void mma_tf32(float& c0, float& c1, float& c2, float& c3,
                                         uint32_t a0, uint32_t a1, uint32_t a2, uint32_t a3,
                                         uint32_t b0, uint32_t b1) {
    asm volatile(
        "mma.sync.aligned.m16n8k8.row.col.f32.tf32.tf32.f32 "
        "{%0,%1,%2,%3}, {%4,%5,%6,%7}, {%8,%9}, {%0,%1,%2,%3};"
        : "+f"(c0), "+f"(c1), "+f"(c2), "+f"(c3)
        : "r"(a0), "r"(a1), "r"(a2), "r"(a3), "r"(b0), "r"(b1));
}

// ---------------- tf32 tensor-core GEMM: C = A @ B^T ----------------
// A [M,K] row-major, B [N,K] row-major. M%128==0, N%128==0, K%32==0.
// batching: z -> Ab = A + (z/hmod)*sA ; Bb = B + (z%hmod)*sB ; Cb = C + z*sC
// CTA 128x128, BK=32, 8 warps, warp tile 64x32 (4x4 of m16n8k8).
#define BK 32
#define LDS_STRIDE 36   // 32 + 4 pad words: fragment LDS conflict-free, v4-store aligned

__global__ __launch_bounds__(256)
void gemm_tc(const float* __restrict__ A, const float* __restrict__ B,
             float* __restrict__ C, int M, int N, int K,
             long sA, long sB, long sC, int hmod)
{
    __shared__ uint32_t As[128 * LDS_STRIDE];
    __shared__ uint32_t Bs[128 * LDS_STRIDE];

    const int tid = threadIdx.x;
    const int wid = tid >> 5, lane = tid & 31;
    const int g = lane >> 2, t = lane & 3;           // groupID / threadID_in_group
    const int z = blockIdx.z;
    const float* Ab = A + (long)(z / hmod) * sA;
    const float* Bb = B + (long)(z % hmod) * sB;
    float* Cb = C + (long)z * sC;
    const int m0 = blockIdx.y * 128;
    const int n0 = blockIdx.x * 128;

    const int wm = (wid & 1) * 64;                   // warp tile origin in M
    const int wn = (wid >> 1) * 32;                  // warp tile origin in N

    float acc[4][4][4];
    #pragma unroll
    for (int m = 0; m < 4; m++)
        #pragma unroll
        for (int n = 0; n < 4; n++)
            #pragma unroll
            for (int r = 0; r < 4; r++) acc[m][n][r] = 0.f;

    const int lrow = tid >> 3;          // 0..31
    const int lc4  = (tid & 7) << 2;    // 0,4,..,28

    for (int k0 = 0; k0 < K; k0 += BK) {
        #pragma unroll
        for (int p = 0; p < 4; p++) {
            int row = lrow + p * 32;
            float4 va = *(const float4*)(Ab + (long)(m0 + row) * K + k0 + lc4);
            uint32_t* dst = &As[row * LDS_STRIDE + lc4];
            dst[0] = f2tf32(va.x); dst[1] = f2tf32(va.y);
            dst[2] = f2tf32(va.z); dst[3] = f2tf32(va.w);
            float4 vb = *(const float4*)(Bb + (long)(n0 + row) * K + k0 + lc4);
            uint32_t* dstb = &Bs[row * LDS_STRIDE + lc4];
            dstb[0] = f2tf32(vb.x); dstb[1] = f2tf32(vb.y);
            dstb[2] = f2tf32(vb.z); dstb[3] = f2tf32(vb.w);
        }
        __syncthreads();

        #pragma unroll
        for (int ks = 0; ks < BK / 8; ks++) {
            const int kk = ks * 8;
            uint32_t af[4][4], bf[4][2];
            #pragma unroll
            for (int m = 0; m < 4; m++) {
                const int r0 = (wm + m * 16 + g) * LDS_STRIDE + kk;
                const int r1 = (wm + m * 16 + g + 8) * LDS_STRIDE + kk;
                af[m][0] = As[r0 + t];
                af[m][1] = As[r1 + t];
                af[m][2] = As[r0 + t + 4];
                af[m][3] = As[r1 + t + 4];
            }
            #pragma unroll
            for (int n = 0; n < 4; n++) {
                const int rn = (wn + n * 8 + g) * LDS_STRIDE + kk;
                bf[n][0] = Bs[rn + t];
                bf[n][1] = Bs[rn + t + 4];
            }
            #pragma unroll
            for (int m = 0; m < 4; m++)
                #pragma unroll
                for (int n = 0; n < 4; n++)
                    mma_tf32(acc[m][n][0], acc[m][n][1], acc[m][n][2], acc[m][n][3],
                             af[m][0], af[m][1], af[m][2], af[m][3],
                             bf[n][0], bf[n][1]);
        }
        __syncthreads();
    }

    #pragma unroll
    for (int m = 0; m < 4; m++) {
        const long row0 = m0 + wm + m * 16 + g;
        #pragma unroll
        for (int n = 0; n < 4; n++) {
            const int col = n0 + wn + n * 8 + 2 * t;
            *(float2*)(Cb + row0 * N + col)       = make_float2(acc[m][n][0], acc[m][n][1]);
            *(float2*)(Cb + (row0 + 8) * N + col) = make_float2(acc[m][n][2], acc[m][n][3]);
        }
    }
}

// ---------------- transpose [H, RKV, HDIM] -> [H, HDIM, RKV] ----------------
__global__ __launch_bounds__(256)
void transpose_up(const float* __restrict__ in, float* __restrict__ out)
{
    __shared__ float t[32][33];
    const int h = blockIdx.z;
    const int r0 = blockIdx.y * 32;   // RKV dim
    const int c0 = blockIdx.x * 32;   // HDIM dim
    const int tx = threadIdx.x & 31, ty0 = threadIdx.x >> 5;
    const float* ip = in + (long)h * RKV * HDIM;
    float* op = out + (long)h * RKV * HDIM;
    #pragma unroll
    for (int r = 0; r < 4; r++) {
        int ty = ty0 + r * 8;
        t[ty][tx] = ip[(long)(r0 + ty) * HDIM + c0 + tx];
    }
    __syncthreads();
    #pragma unroll
    for (int r = 0; r < 4; r++) {
        int ty = ty0 + r * 8;
        op[(long)(c0 + ty) * RKV + r0 + tx] = t[tx][ty];
    }
}

// ---------------- tensor-core flash attention (tf32 mma, ALiBi + causal) ----------------
// BM=64 q-rows/CTA, BN=64 kv per iter, d=128. 256 threads, 8 warps.
// S phase: warp grid 4(M)x2(N), warp tile 16x32.  PV: 4(M)x2(d), warp tile 16x64.
// Softmax state is per ROW; each row's 64 cols are split across warps nw=0/1, so the
// row max and row sum are combined across the two warps through smem (Red/Sum).
#define FQS 132
#define FVS 136
#define FPS 68
#define FLASH2_SMEM_WORDS (64*FQS + 64*FVS + 64*FPS + 256)
#define FLASH2_SMEM_BYTES (FLASH2_SMEM_WORDS * 4)   // 87040

__global__ __launch_bounds__(256)
void flash_tc(const float* __restrict__ Q, const float* __restrict__ Kg,
              const float* __restrict__ Vg, float* __restrict__ O)
{
    extern __shared__ uint32_t sm[];
    uint32_t* Qs  = sm;                       // [64][132] tf32
    uint32_t* KVs = sm + 64*FQS;              // K:[64][132] / V:[64][136] (reused)
    uint32_t* Ps  = sm + 64*FQS + 64*FVS;     // [64][68] tf32
    float*    Red = (float*)(sm + 64*FQS + 64*FVS + 64*FPS);   // [2][64] partial max
    float*    Sum = Red + 128;                                  // [2][64] partial sum

    const int bh = blockIdx.y;
    const int b  = bh >> 4, h = bh & 15;
    const int qt = blockIdx.x;
    const int q0 = qt * 64;
    const int tid = threadIdx.x;
    const int wid = tid >> 5, lane = tid & 31;
    const int g = lane >> 2, t = lane & 3;
    const int mw = wid & 3;                   // M strip (16 rows)
    const int nw = wid >> 2;                  // N strip

    const float slope = exp2f(-0.5f * (float)(h + 1));
    const float scale = 0.08838834764831843f;

    const float* Qbase = Q  + ((long)(b*SEQ + q0)) * DMODEL + h*HDIM;
    const float* Kbase = Kg + ((long)(b*NHEAD + h)) * SEQ * HDIM;
    const float* Vbase = Vg + ((long)(b*NHEAD + h)) * SEQ * HDIM;

    // load Q tile 64x128, convert tf32
    #pragma unroll
    for (int p = 0; p < 8; p++) {
        int idx = tid + p*256;
        int row = idx >> 5, c4 = (idx & 31) << 2;
        float4 v = *(const float4*)(Qbase + (long)row*DMODEL + c4);
        uint32_t* d = &Qs[row*FQS + c4];
        d[0] = f2tf32(v.x); d[1] = f2tf32(v.y); d[2] = f2tf32(v.z); d[3] = f2tf32(v.w);
    }

    const int r0 = mw*16 + g, r1 = r0 + 8;    // this thread's q rows (local)
    const int qi0 = q0 + r0, qi1 = q0 + r1;

    float o[8][4];
    #pragma unroll
    for (int n = 0; n < 8; n++)
        #pragma unroll
        for (int r = 0; r < 4; r++) o[n][r] = 0.f;
    float m0 = -INFINITY, m1 = -INFINITY, l0 = 0.f, l1 = 0.f;

    for (int kt = 0; kt <= qt; kt++) {
        const int k0 = kt * 64;
        __syncthreads();   // prev PV reads of KVs/Ps done (kt=0: Q stores visible after next barrier)
        // load K tile 64x128 (stride 132)
        #pragma unroll
        for (int p = 0; p < 8; p++) {
            int idx = tid + p*256;
            int row = idx >> 5, c4 = (idx & 31) << 2;
            float4 v = *(const float4*)(Kbase + (long)(k0+row)*HDIM + c4);
            uint32_t* d = &KVs[row*FQS + c4];
            d[0] = f2tf32(v.x); d[1] = f2tf32(v.y); d[2] = f2tf32(v.z); d[3] = f2tf32(v.w);
        }
        __syncthreads();

        // S = Q @ K^T  (warp tile 16x32: 4 n-subtiles)
        float s[4][4];
        #pragma unroll
        for (int n = 0; n < 4; n++)
            #pragma unroll
            for (int r = 0; r < 4; r++) s[n][r] = 0.f;
        #pragma unroll
        for (int ks = 0; ks < 16; ks++) {
            const int kk = ks * 8;
            uint32_t a0 = Qs[r0*FQS + kk + t];
            uint32_t a1 = Qs[r1*FQS + kk + t];
            uint32_t a2 = Qs[r0*FQS + kk + t + 4];
            uint32_t a3 = Qs[r1*FQS + kk + t + 4];
            #pragma unroll
            for (int n = 0; n < 4; n++) {
                const int nr = nw*32 + n*8 + g;
                uint32_t b0 = KVs[nr*FQS + kk + t];
                uint32_t b1 = KVs[nr*FQS + kk + t + 4];
                mma_tf32(s[n][0], s[n][1], s[n][2], s[n][3], a0, a1, a2, a3, b0, b1);
            }
        }

        // scale + ALiBi + causal, partial (this warp's 32-col half) row max
        float rv0 = -INFINITY, rv1 = -INFINITY;
        #pragma unroll
        for (int n = 0; n < 4; n++) {
            const int kj = k0 + nw*32 + n*8 + 2*t;
            s[n][0] = (kj   <= qi0) ? fmaf(s[n][0], scale, -slope*(float)(qi0-kj))   : -INFINITY;
            s[n][1] = (kj+1 <= qi0) ? fmaf(s[n][1], scale, -slope*(float)(qi0-kj-1)) : -INFINITY;
            s[n][2] = (kj   <= qi1) ? fmaf(s[n][2], scale, -slope*(float)(qi1-kj))   : -INFINITY;
            s[n][3] = (kj+1 <= qi1) ? fmaf(s[n][3], scale, -slope*(float)(qi1-kj-1)) : -INFINITY;
            rv0 = fmaxf(rv0, fmaxf(s[n][0], s[n][1]));
            rv1 = fmaxf(rv1, fmaxf(s[n][2], s[n][3]));
        }
        rv0 = fmaxf(rv0, __shfl_xor_sync(0xffffffffu, rv0, 1));
        rv0 = fmaxf(rv0, __shfl_xor_sync(0xffffffffu, rv0, 2));
        rv1 = fmaxf(rv1, __shfl_xor_sync(0xffffffffu, rv1, 1));
        rv1 = fmaxf(rv1, __shfl_xor_sync(0xffffffffu, rv1, 2));
        if (t == 0) { Red[nw*64 + r0] = rv0; Red[nw*64 + r1] = rv1; }
        __syncthreads();   // (A) partial maxes visible; all warps done reading K

        // issue V loads now (overwrites K buffer; overlaps with softmax math below)
        #pragma unroll
        for (int p = 0; p < 8; p++) {
            int idx = tid + p*256;
            int row = idx >> 5, c4 = (idx & 31) << 2;
            float4 v = *(const float4*)(Vbase + (long)(k0+row)*HDIM + c4);
            uint32_t* d = &KVs[row*FVS + c4];
            d[0] = f2tf32(v.x); d[1] = f2tf32(v.y); d[2] = f2tf32(v.z); d[3] = f2tf32(v.w);
        }

        // combined (full-row) max -> consistent softmax across both warp halves
        rv0 = fmaxf(Red[r0], Red[64 + r0]);
        rv1 = fmaxf(Red[r1], Red[64 + r1]);
        const float m0n = fmaxf(m0, rv0), m1n = fmaxf(m1, rv1);
        const float al0 = __expf(m0 - m0n), al1 = __expf(m1 - m1n);
        m0 = m0n; m1 = m1n;
        float rs0 = 0.f, rs1 = 0.f;
        #pragma unroll
        for (int n = 0; n < 4; n++) {
            float p00 = __expf(s[n][0] - m0n), p01 = __expf(s[n][1] - m0n);
            float p10 = __expf(s[n][2] - m1n), p11 = __expf(s[n][3] - m1n);
            rs0 += p00 + p01; rs1 += p10 + p11;
            const int cn = nw*32 + n*8 + 2*t;
            Ps[r0*FPS + cn] = f2tf32(p00); Ps[r0*FPS + cn + 1] = f2tf32(p01);
            Ps[r1*FPS + cn] = f2tf32(p10); Ps[r1*FPS + cn + 1] = f2tf32(p11);
        }
        rs0 += __shfl_xor_sync(0xffffffffu, rs0, 1);
        rs0 += __shfl_xor_sync(0xffffffffu, rs0, 2);
        rs1 += __shfl_xor_sync(0xffffffffu, rs1, 1);
        rs1 += __shfl_xor_sync(0xffffffffu, rs1, 2);
        if (t == 0) { Sum[nw*64 + r0] = rs0; Sum[nw*64 + r1] = rs1; }
        __syncthreads();   // (B) V, Ps, partial sums all complete

        // combined row sum; update l and rescale o
        rs0 = Sum[r0] + Sum[64 + r0];
        rs1 = Sum[r1] + Sum[64 + r1];
        l0 = l0 * al0 + rs0; l1 = l1 * al1 + rs1;
        #pragma unroll
        for (int n = 0; n < 8; n++) {
            o[n][0] *= al0; o[n][1] *= al0; o[n][2] *= al1; o[n][3] *= al1;
        }

        // O += P @ V  (warp tile 16x64: 8 d-subtiles)
        #pragma unroll
        for (int ks = 0; ks < 8; ks++) {
            const int kk = ks * 8;
            uint32_t a0 = Ps[r0*FPS + kk + t];
            uint32_t a1 = Ps[r1*FPS + kk + t];
            uint32_t a2 = Ps[r0*FPS + kk + t + 4];
            uint32_t a3 = Ps[r1*FPS + kk + t + 4];
            #pragma unroll
            for (int n = 0; n < 8; n++) {
                const int col = nw*64 + n*8 + g;
                uint32_t b0 = KVs[(kk + t)*FVS + col];
                uint32_t b1 = KVs[(kk + t + 4)*FVS + col];
                mma_tf32(o[n][0], o[n][1], o[n][2], o[n][3], a0, a1, a2, a3, b0, b1);
            }
        }
    }

    // normalize + write O[b, q, h*128 + col]
    const float inv0 = 1.f / l0, inv1 = 1.f / l1;
    const long row0 = (long)(b*SEQ + q0 + r0);
    const long row1 = (long)(b*SEQ + q0 + r1);
    #pragma unroll
    for (int n = 0; n < 8; n++) {
        const int col = h*HDIM + nw*64 + n*8 + 2*t;
        *(float2*)(O + row0*DMODEL + col) = make_float2(o[n][0]*inv0, o[n][1]*inv0);
        *(float2*)(O + row1*DMODEL + col) = make_float2(o[n][2]*inv1, o[n][3]*inv1);
    }
}

// ---------------- launch ----------------
extern "C" void kernel_launch(void* const* d_in, const int* in_sizes, int n_in,
                              void* d_out, int out_size)
{
    const float* X        = (const float*)d_in[0];
    const float* Wq_down  = (const float*)d_in[1];   // [1536, 2048]
    const float* Wq_up    = (const float*)d_in[2];   // [2048, 1536]
    const float* Wkv_down = (const float*)d_in[3];   // [512, 2048]
    const float* k_up     = (const float*)d_in[4];   // [16, 512, 128]
    const float* v_up     = (const float*)d_in[5];   // [16, 512, 128]
    const float* Wo       = (const float*)d_in[6];   // [2048, 2048]
    float* out = (float*)d_out;

    float *xq, *q, *c, *kb, *vb, *ob, *kuT, *vuT;
    cudaGetSymbolAddress((void**)&xq,  g_xq);
    cudaGetSymbolAddress((void**)&q,   g_q);
    cudaGetSymbolAddress((void**)&c,   g_c);
    cudaGetSymbolAddress((void**)&kb,  g_k);
    cudaGetSymbolAddress((void**)&vb,  g_v);
    cudaGetSymbolAddress((void**)&ob,  g_o);
    cudaGetSymbolAddress((void**)&kuT, g_kuT);
    cudaGetSymbolAddress((void**)&vuT, g_vuT);

    cudaFuncSetAttribute(flash_tc,
                         cudaFuncAttributeMaxDynamicSharedMemorySize, FLASH2_SMEM_BYTES);

    dim3 blk(256);

    // 0) transpose k_up/v_up -> [H, HDIM, RKV] so all GEMMs consume K-major B
    transpose_up<<<dim3(HDIM/32, RKV/32, NHEAD), blk>>>(k_up, kuT);
    transpose_up<<<dim3(HDIM/32, RKV/32, NHEAD), blk>>>(v_up, vuT);

    // 1) Xq = X @ Wq_down^T : [4096,1536]
    gemm_tc<<<dim3(RQ/128, MTOT/128, 1), blk>>>(
        X, Wq_down, xq, MTOT, RQ, DMODEL, 0, 0, 0, 1);
    // 2) Q = Xq @ Wq_up^T : [4096,2048]
    gemm_tc<<<dim3(DMODEL/128, MTOT/128, 1), blk>>>(
        xq, Wq_up, q, MTOT, DMODEL, RQ, 0, 0, 0, 1);
    // 3) C = X @ Wkv_down^T : [4096,512]
    gemm_tc<<<dim3(RKV/128, MTOT/128, 1), blk>>>(
        X, Wkv_down, c, MTOT, RKV, DMODEL, 0, 0, 0, 1);
    // 4) K[b,h] = C_b @ kuT[h]^T : batched 32x [2048,128]
    gemm_tc<<<dim3(1, SEQ/128, BATCH*NHEAD), blk>>>(
        c, kuT, kb, SEQ, HDIM, RKV,
        (long)SEQ*RKV, (long)HDIM*RKV, (long)SEQ*HDIM, NHEAD);
    // 5) V likewise
    gemm_tc<<<dim3(1, SEQ/128, BATCH*NHEAD), blk>>>(
        c, vuT, vb, SEQ, HDIM, RKV,
        (long)SEQ*RKV, (long)HDIM*RKV, (long)SEQ*HDIM, NHEAD);
    // 6) tensor-core causal+ALiBi flash attention -> ob [B,L,H*d]
    flash_tc<<<dim3(SEQ/64, BATCH*NHEAD), blk, FLASH2_SMEM_BYTES>>>(q, kb, vb, ob);
    // 7) out = ob @ Wo^T : [4096,2048]
    gemm_tc<<<dim3(DMODEL/128, MTOT/128, 1), blk>>>(
        ob, Wo, out, MTOT, DMODEL, DMODEL, 0, 0, 0, 1);
}

// round 7
// speedup vs baseline: 3.8769x; 1.1476x over previous
#include <cuda_runtime.h>
#include <cstdint>
#include <math.h>

// ---------------- problem constants ----------------
#define BATCH 2
#define SEQ   2048
#define DMODEL 2048
#define NHEAD 16
#define HDIM  128
#define RQ    1536
#define RKV   512
#define MTOT  (BATCH*SEQ)          // 4096

// ---------------- scratch (allocation-free: __device__ globals) ----------------
__device__ float g_xq[(size_t)MTOT * RQ];            // X @ Wq_down^T
__device__ float g_q [(size_t)MTOT * DMODEL];        // Q  [B*L, H*d]
__device__ float g_c [(size_t)MTOT * RKV];           // latent C
__device__ float g_k [(size_t)BATCH*NHEAD*SEQ*HDIM]; // K [B,H,L,d]
__device__ float g_v [(size_t)BATCH*NHEAD*SEQ*HDIM]; // V [B,H,L,d]
__device__ float g_o [(size_t)MTOT * DMODEL];        // attn out [B,L,H*d]
__device__ float g_kuT[(size_t)NHEAD*HDIM*RKV];      // k_up transposed: [H, d, r]
__device__ float g_vuT[(size_t)NHEAD*HDIM*RKV];      // v_up transposed

// ---------------- helpers ----------------
__device__ __forceinline__ uint32_t smem_u32(const void* p) {
    uint32_t a;
    asm("{ .reg .u64 t; cvta.to.shared.u64 t, %1; cvt.u32.u64 %0, t; }" : "=r"(a) : "l"(p));
    return a;
}
__device__ __forceinline__ uint32_t f2tf32(float x) {
    uint32_t r;
    asm("cvt.rna.tf32.f32 %0, %1;" : "=r"(r) : "f"(x));
    return r;
}
__device__ __forceinline__ uint32_t u2tf32(uint32_t bits) {
    uint32_t r;
    asm("cvt.rna.tf32.f32 %0, %1;" : "=r"(r) : "f"(__uint_as_float(bits)));
    return r;
}
__device__ __forceinline__ void cp16(uint32_t saddr, const void* gaddr) {
    asm volatile("cp.async.cg.shared.global [%0], [%1], 16;" :: "r"(saddr), "l"(gaddr));
}
#define CP_COMMIT()  asm volatile("cp.async.commit_group;" ::: "memory")
#define CP_WAIT_1()  asm volatile("cp.async.wait_group 1;" ::: "memory")
#define CP_WAIT_0()  asm volatile("cp.async.wait_group 0;" ::: "memory")

// mma.sync m16n8k8 tf32: D = A(16x8 row) * B(8x8 col) + C, fp32 accum.
__device__ __forceinline__ void mma_tf32(float& c0, float& c1, float& c2, float& c3,
                                         uint32_t a0, uint32_t a1, uint32_t a2, uint32_t a3,
                                         uint32_t b0, uint32_t b1) {
    asm volatile(
        "mma.sync.aligned.m16n8k8.row.col.f32.tf32.tf32.f32 "
        "{%0,%1,%2,%3}, {%4,%5,%6,%7}, {%8,%9}, {%0,%1,%2,%3};"
        : "+f"(c0), "+f"(c1), "+f"(c2), "+f"(c3)
        : "r"(a0), "r"(a1), "r"(a2), "r"(a3), "r"(b0), "r"(b1));
}

// ---------------- tf32 tensor-core GEMM: C = A @ B^T (cp.async double-buffered) ----------------
// A [M,K] row-major, B [N,K] row-major. M%128==0, N%128==0, K%32==0.
// batching: z -> Ab = A + (z/hmod)*sA ; Bb = B + (z%hmod)*sB ; Cb = C + z*sC
// CTA 128x128, BK=32, 8 warps, warp tile 64x32 (4x4 of m16n8k8).
// Smem holds RAW fp32 (cp.async); tf32 cvt happens on the fragment-load path.
#define BK 32
#define ST 36                       // row stride in words (32 + 4 pad)
#define GEMM_BUF_WORDS (128 * ST)   // 4608 words = 18432 B per tile buffer
#define GEMM_SMEM_BYTES (4 * GEMM_BUF_WORDS * 4)   // A0,B0,A1,B1 = 73728 B

__global__ __launch_bounds__(256)
void gemm_tc(const float* __restrict__ A, const float* __restrict__ B,
             float* __restrict__ C, int M, int N, int K,
             long sA, long sB, long sC, int hmod)
{
    extern __shared__ uint32_t sh[];
    const uint32_t sbase = smem_u32(sh);

    const int tid = threadIdx.x;
    const int wid = tid >> 5, lane = tid & 31;
    const int g = lane >> 2, t = lane & 3;           // groupID / threadID_in_group
    const int z = blockIdx.z;
    const float* Ab = A + (long)(z / hmod) * sA;
    const float* Bb = B + (long)(z % hmod) * sB;
    float* Cb = C + (long)z * sC;
    const int m0 = blockIdx.y * 128;
    const int n0 = blockIdx.x * 128;

    const int wm = (wid & 1) * 64;                   // warp tile origin in M
    const int wn = (wid >> 1) * 32;                  // warp tile origin in N

    float acc[4][4][4];
    #pragma unroll
    for (int m = 0; m < 4; m++)
        #pragma unroll
        for (int n = 0; n < 4; n++)
            #pragma unroll
            for (int r = 0; r < 4; r++) acc[m][n][r] = 0.f;

    const int lrow = tid >> 3;          // 0..31
    const int lc4  = (tid & 7) << 2;    // 0,4,..,28

    // issue cp.async for K-chunk at k0 into buffer b (A + B tiles)
    auto issue = [&](int k0, int b) {
        const uint32_t abase = sbase + (uint32_t)b * (2u * GEMM_BUF_WORDS * 4u);
        const uint32_t bbase = abase + GEMM_BUF_WORDS * 4u;
        #pragma unroll
        for (int p = 0; p < 4; p++) {
            const int row = lrow + p * 32;
            const uint32_t so = (uint32_t)(row * ST + lc4) * 4u;
            cp16(abase + so, Ab + (long)(m0 + row) * K + k0 + lc4);
            cp16(bbase + so, Bb + (long)(n0 + row) * K + k0 + lc4);
        }
        CP_COMMIT();
    };

    const int KT = K >> 5;
    issue(0, 0);

    for (int kt = 0; kt < KT; kt++) {
        if (kt + 1 < KT) { issue((kt + 1) << 5, (kt + 1) & 1); CP_WAIT_1(); }
        else             { CP_WAIT_0(); }
        __syncthreads();

        const uint32_t* Asb = sh + (size_t)(kt & 1) * (2 * GEMM_BUF_WORDS);
        const uint32_t* Bsb = Asb + GEMM_BUF_WORDS;

        #pragma unroll
        for (int ks = 0; ks < BK / 8; ks++) {
            const int kk = ks * 8;
            uint32_t af[4][4], bf[4][2];
            #pragma unroll
            for (int m = 0; m < 4; m++) {
                const int r0 = (wm + m * 16 + g) * ST + kk;
                const int r1 = (wm + m * 16 + g + 8) * ST + kk;
                af[m][0] = u2tf32(Asb[r0 + t]);
                af[m][1] = u2tf32(Asb[r1 + t]);
                af[m][2] = u2tf32(Asb[r0 + t + 4]);
                af[m][3] = u2tf32(Asb[r1 + t + 4]);
            }
            #pragma unroll
            for (int n = 0; n < 4; n++) {
                const int rn = (wn + n * 8 + g) * ST + kk;
                bf[n][0] = u2tf32(Bsb[rn + t]);
                bf[n][1] = u2tf32(Bsb[rn + t + 4]);
            }
            #pragma unroll
            for (int m = 0; m < 4; m++)
                #pragma unroll
                for (int n = 0; n < 4; n++)
                    mma_tf32(acc[m][n][0], acc[m][n][1], acc[m][n][2], acc[m][n][3],
                             af[m][0], af[m][1], af[m][2], af[m][3],
                             bf[n][0], bf[n][1]);
        }
        __syncthreads();
    }

    #pragma unroll
    for (int m = 0; m < 4; m++) {
        const long row0 = m0 + wm + m * 16 + g;
        #pragma unroll
        for (int n = 0; n < 4; n++) {
            const int col = n0 + wn + n * 8 + 2 * t;
            *(float2*)(Cb + row0 * N + col)       = make_float2(acc[m][n][0], acc[m][n][1]);
            *(float2*)(Cb + (row0 + 8) * N + col) = make_float2(acc[m][n][2], acc[m][n][3]);
        }
    }
}

// ---------------- transpose [H, RKV, HDIM] -> [H, HDIM, RKV] ----------------
__global__ __launch_bounds__(256)
void transpose_up(const float* __restrict__ in, float* __restrict__ out)
{
    __shared__ float t[32][33];
    const int h = blockIdx.z;
    const int r0 = blockIdx.y * 32;   // RKV dim
    const int c0 = blockIdx.x * 32;   // HDIM dim
    const int tx = threadIdx.x & 31, ty0 = threadIdx.x >> 5;
    const float* ip = in + (long)h * RKV * HDIM;
    float* op = out + (long)h * RKV * HDIM;
    #pragma unroll
    for (int r = 0; r < 4; r++) {
        int ty = ty0 + r * 8;
        t[ty][tx] = ip[(long)(r0 + ty) * HDIM + c0 + tx];
    }
    __syncthreads();
    #pragma unroll
    for (int r = 0; r < 4; r++) {
        int ty = ty0 + r * 8;
        op[(long)(c0 + ty) * RKV + r0 + tx] = t[tx][ty];
    }
}

// ---------------- tensor-core flash attention (tf32 mma, ALiBi + causal) ----------------
// BM=64 q-rows/CTA, BN=64 kv per iter, d=128. 256 threads, 8 warps.
// S phase: warp grid 4(M)x2(N), warp tile 16x32.  PV: 4(M)x2(d), warp tile 16x64.
// Softmax state is per ROW; each row's 64 cols are split across warps nw=0/1, so the
// row max and row sum are combined across the two warps through smem (Red/Sum).
#define FQS 132
#define FVS 136
#define FPS 68
#define FLASH2_SMEM_WORDS (64*FQS + 64*FVS + 64*FPS + 256)
#define FLASH2_SMEM_BYTES (FLASH2_SMEM_WORDS * 4)   // 87040

__global__ __launch_bounds__(256)
void flash_tc(const float* __restrict__ Q, const float* __restrict__ Kg,
              const float* __restrict__ Vg, float* __restrict__ O)
{
    extern __shared__ uint32_t sm[];
    uint32_t* Qs  = sm;                       // [64][132] tf32
    uint32_t* KVs = sm + 64*FQS;              // K:[64][132] / V:[64][136] (reused)
    uint32_t* Ps  = sm + 64*FQS + 64*FVS;     // [64][68] tf32
    float*    Red = (float*)(sm + 64*FQS + 64*FVS + 64*FPS);   // [2][64] partial max
    float*    Sum = Red + 128;                                  // [2][64] partial sum

    const int bh = blockIdx.y;
    const int b  = bh >> 4, h = bh & 15;
    const int qt = blockIdx.x;
    const int q0 = qt * 64;
    const int tid = threadIdx.x;
    const int wid = tid >> 5, lane = tid & 31;
    const int g = lane >> 2, t = lane & 3;
    const int mw = wid & 3;                   // M strip (16 rows)
    const int nw = wid >> 2;                  // N strip

    const float slope = exp2f(-0.5f * (float)(h + 1));
    const float scale = 0.08838834764831843f;

    const float* Qbase = Q  + ((long)(b*SEQ + q0)) * DMODEL + h*HDIM;
    const float* Kbase = Kg + ((long)(b*NHEAD + h)) * SEQ * HDIM;
    const float* Vbase = Vg + ((long)(b*NHEAD + h)) * SEQ * HDIM;

    // load Q tile 64x128, convert tf32
    #pragma unroll
    for (int p = 0; p < 8; p++) {
        int idx = tid + p*256;
        int row = idx >> 5, c4 = (idx & 31) << 2;
        float4 v = *(const float4*)(Qbase + (long)row*DMODEL + c4);
        uint32_t* d = &Qs[row*FQS + c4];
        d[0] = f2tf32(v.x); d[1] = f2tf32(v.y); d[2] = f2tf32(v.z); d[3] = f2tf32(v.w);
    }

    const int r0 = mw*16 + g, r1 = r0 + 8;    // this thread's q rows (local)
    const int qi0 = q0 + r0, qi1 = q0 + r1;

    float o[8][4];
    #pragma unroll
    for (int n = 0; n < 8; n++)
        #pragma unroll
        for (int r = 0; r < 4; r++) o[n][r] = 0.f;
    float m0 = -INFINITY, m1 = -INFINITY, l0 = 0.f, l1 = 0.f;

    for (int kt = 0; kt <= qt; kt++) {
        const int k0 = kt * 64;
        __syncthreads();   // prev PV reads of KVs/Ps done (kt=0: Q stores visible after next barrier)
        // load K tile 64x128 (stride 132)
        #pragma unroll
        for (int p = 0; p < 8; p++) {
            int idx = tid + p*256;
            int row = idx >> 5, c4 = (idx & 31) << 2;
            float4 v = *(const float4*)(Kbase + (long)(k0+row)*HDIM + c4);
            uint32_t* d = &KVs[row*FQS + c4];
            d[0] = f2tf32(v.x); d[1] = f2tf32(v.y); d[2] = f2tf32(v.z); d[3] = f2tf32(v.w);
        }
        __syncthreads();

        // S = Q @ K^T  (warp tile 16x32: 4 n-subtiles)
        float s[4][4];
        #pragma unroll
        for (int n = 0; n < 4; n++)
            #pragma unroll
            for (int r = 0; r < 4; r++) s[n][r] = 0.f;
        #pragma unroll
        for (int ks = 0; ks < 16; ks++) {
            const int kk = ks * 8;
            uint32_t a0 = Qs[r0*FQS + kk + t];
            uint32_t a1 = Qs[r1*FQS + kk + t];
            uint32_t a2 = Qs[r0*FQS + kk + t + 4];
            uint32_t a3 = Qs[r1*FQS + kk + t + 4];
            #pragma unroll
            for (int n = 0; n < 4; n++) {
                const int nr = nw*32 + n*8 + g;
                uint32_t b0 = KVs[nr*FQS + kk + t];
                uint32_t b1 = KVs[nr*FQS + kk + t + 4];
                mma_tf32(s[n][0], s[n][1], s[n][2], s[n][3], a0, a1, a2, a3, b0, b1);
            }
        }

        // scale + ALiBi + causal, partial (this warp's 32-col half) row max
        float rv0 = -INFINITY, rv1 = -INFINITY;
        #pragma unroll
        for (int n = 0; n < 4; n++) {
            const int kj = k0 + nw*32 + n*8 + 2*t;
            s[n][0] = (kj   <= qi0) ? fmaf(s[n][0], scale, -slope*(float)(qi0-kj))   : -INFINITY;
            s[n][1] = (kj+1 <= qi0) ? fmaf(s[n][1], scale, -slope*(float)(qi0-kj-1)) : -INFINITY;
            s[n][2] = (kj   <= qi1) ? fmaf(s[n][2], scale, -slope*(float)(qi1-kj))   : -INFINITY;
            s[n][3] = (kj+1 <= qi1) ? fmaf(s[n][3], scale, -slope*(float)(qi1-kj-1)) : -INFINITY;
            rv0 = fmaxf(rv0, fmaxf(s[n][0], s[n][1]));
            rv1 = fmaxf(rv1, fmaxf(s[n][2], s[n][3]));
        }
        rv0 = fmaxf(rv0, __shfl_xor_sync(0xffffffffu, rv0, 1));
        rv0 = fmaxf(rv0, __shfl_xor_sync(0xffffffffu, rv0, 2));
        rv1 = fmaxf(rv1, __shfl_xor_sync(0xffffffffu, rv1, 1));
        rv1 = fmaxf(rv1, __shfl_xor_sync(0xffffffffu, rv1, 2));
        if (t == 0) { Red[nw*64 + r0] = rv0; Red[nw*64 + r1] = rv1; }
        __syncthreads();   // (A) partial maxes visible; all warps done reading K

        // issue V loads now (overwrites K buffer; overlaps with softmax math below)
        #pragma unroll
        for (int p = 0; p < 8; p++) {
            int idx = tid + p*256;
            int row = idx >> 5, c4 = (idx & 31) << 2;
            float4 v = *(const float4*)(Vbase + (long)(k0+row)*HDIM + c4);
            uint32_t* d = &KVs[row*FVS + c4];
            d[0] = f2tf32(v.x); d[1] = f2tf32(v.y); d[2] = f2tf32(v.z); d[3] = f2tf32(v.w);
        }

        // combined (full-row) max -> consistent softmax across both warp halves
        rv0 = fmaxf(Red[r0], Red[64 + r0]);
        rv1 = fmaxf(Red[r1], Red[64 + r1]);
        const float m0n = fmaxf(m0, rv0), m1n = fmaxf(m1, rv1);
        const float al0 = __expf(m0 - m0n), al1 = __expf(m1 - m1n);
        m0 = m0n; m1 = m1n;
        float rs0 = 0.f, rs1 = 0.f;
        #pragma unroll
        for (int n = 0; n < 4; n++) {
            float p00 = __expf(s[n][0] - m0n), p01 = __expf(s[n][1] - m0n);
            float p10 = __expf(s[n][2] - m1n), p11 = __expf(s[n][3] - m1n);
            rs0 += p00 + p01; rs1 += p10 + p11;
            const int cn = nw*32 + n*8 + 2*t;
            Ps[r0*FPS + cn] = f2tf32(p00); Ps[r0*FPS + cn + 1] = f2tf32(p01);
            Ps[r1*FPS + cn] = f2tf32(p10); Ps[r1*FPS + cn + 1] = f2tf32(p11);
        }
        rs0 += __shfl_xor_sync(0xffffffffu, rs0, 1);
        rs0 += __shfl_xor_sync(0xffffffffu, rs0, 2);
        rs1 += __shfl_xor_sync(0xffffffffu, rs1, 1);
        rs1 += __shfl_xor_sync(0xffffffffu, rs1, 2);
        if (t == 0) { Sum[nw*64 + r0] = rs0; Sum[nw*64 + r1] = rs1; }
        __syncthreads();   // (B) V, Ps, partial sums all complete

        // combined row sum; update l and rescale o
        rs0 = Sum[r0] + Sum[64 + r0];
        rs1 = Sum[r1] + Sum[64 + r1];
        l0 = l0 * al0 + rs0; l1 = l1 * al1 + rs1;
        #pragma unroll
        for (int n = 0; n < 8; n++) {
            o[n][0] *= al0; o[n][1] *= al0; o[n][2] *= al1; o[n][3] *= al1;
        }

        // O += P @ V  (warp tile 16x64: 8 d-subtiles)
        #pragma unroll
        for (int ks = 0; ks < 8; ks++) {
            const int kk = ks * 8;
            uint32_t a0 = Ps[r0*FPS + kk + t];
            uint32_t a1 = Ps[r1*FPS + kk + t];
            uint32_t a2 = Ps[r0*FPS + kk + t + 4];
            uint32_t a3 = Ps[r1*FPS + kk + t + 4];
            #pragma unroll
            for (int n = 0; n < 8; n++) {
                const int col = nw*64 + n*8 + g;
                uint32_t b0 = KVs[(kk + t)*FVS + col];
                uint32_t b1 = KVs[(kk + t + 4)*FVS + col];
                mma_tf32(o[n][0], o[n][1], o[n][2], o[n][3], a0, a1, a2, a3, b0, b1);
            }
        }
    }

    // normalize + write O[b, q, h*128 + col]
    const float inv0 = 1.f / l0, inv1 = 1.f / l1;
    const long row0 = (long)(b*SEQ + q0 + r0);
    const long row1 = (long)(b*SEQ + q0 + r1);
    #pragma unroll
    for (int n = 0; n < 8; n++) {
        const int col = h*HDIM + nw*64 + n*8 + 2*t;
        *(float2*)(O + row0*DMODEL + col) = make_float2(o[n][0]*inv0, o[n][1]*inv0);
        *(float2*)(O + row1*DMODEL + col) = make_float2(o[n][2]*inv1, o[n][3]*inv1);
    }
}

// ---------------- launch ----------------
extern "C" void kernel_launch(void* const* d_in, const int* in_sizes, int n_in,
                              void* d_out, int out_size)
{
    const float* X        = (const float*)d_in[0];
    const float* Wq_down  = (const float*)d_in[1];   // [1536, 2048]
    const float* Wq_up    = (const float*)d_in[2];   // [2048, 1536]
    const float* Wkv_down = (const float*)d_in[3];   // [512, 2048]
    const float* k_up     = (const float*)d_in[4];   // [16, 512, 128]
    const float* v_up     = (const float*)d_in[5];   // [16, 512, 128]
    const float* Wo       = (const float*)d_in[6];   // [2048, 2048]
    float* out = (float*)d_out;

    float *xq, *q, *c, *kb, *vb, *ob, *kuT, *vuT;
    cudaGetSymbolAddress((void**)&xq,  g_xq);
    cudaGetSymbolAddress((void**)&q,   g_q);
    cudaGetSymbolAddress((void**)&c,   g_c);
    cudaGetSymbolAddress((void**)&kb,  g_k);
    cudaGetSymbolAddress((void**)&vb,  g_v);
    cudaGetSymbolAddress((void**)&ob,  g_o);
    cudaGetSymbolAddress((void**)&kuT, g_kuT);
    cudaGetSymbolAddress((void**)&vuT, g_vuT);

    cudaFuncSetAttribute(gemm_tc,
                         cudaFuncAttributeMaxDynamicSharedMemorySize, GEMM_SMEM_BYTES);
    cudaFuncSetAttribute(flash_tc,
                         cudaFuncAttributeMaxDynamicSharedMemorySize, FLASH2_SMEM_BYTES);

    dim3 blk(256);

    // 0) transpose k_up/v_up -> [H, HDIM, RKV] so all GEMMs consume K-major B
    transpose_up<<<dim3(HDIM/32, RKV/32, NHEAD), blk>>>(k_up, kuT);
    transpose_up<<<dim3(HDIM/32, RKV/32, NHEAD), blk>>>(v_up, vuT);

    // 1) Xq = X @ Wq_down^T : [4096,1536]
    gemm_tc<<<dim3(RQ/128, MTOT/128, 1), blk, GEMM_SMEM_BYTES>>>(
        X, Wq_down, xq, MTOT, RQ, DMODEL, 0, 0, 0, 1);
    // 2) Q = Xq @ Wq_up^T : [4096,2048]
    gemm_tc<<<dim3(DMODEL/128, MTOT/128, 1), blk, GEMM_SMEM_BYTES>>>(
        xq, Wq_up, q, MTOT, DMODEL, RQ, 0, 0, 0, 1);
    // 3) C = X @ Wkv_down^T : [4096,512]
    gemm_tc<<<dim3(RKV/128, MTOT/128, 1), blk, GEMM_SMEM_BYTES>>>(
        X, Wkv_down, c, MTOT, RKV, DMODEL, 0, 0, 0, 1);
    // 4) K[b,h] = C_b @ kuT[h]^T : batched 32x [2048,128]
    gemm_tc<<<dim3(1, SEQ/128, BATCH*NHEAD), blk, GEMM_SMEM_BYTES>>>(
        c, kuT, kb, SEQ, HDIM, RKV,
        (long)SEQ*RKV, (long)HDIM*RKV, (long)SEQ*HDIM, NHEAD);
    // 5) V likewise
    gemm_tc<<<dim3(1, SEQ/128, BATCH*NHEAD), blk, GEMM_SMEM_BYTES>>>(
        c, vuT, vb, SEQ, HDIM, RKV,
        (long)SEQ*RKV, (long)HDIM*RKV, (long)SEQ*HDIM, NHEAD);
    // 6) tensor-core causal+ALiBi flash attention -> ob [B,L,H*d]
    flash_tc<<<dim3(SEQ/64, BATCH*NHEAD), blk, FLASH2_SMEM_BYTES>>>(q, kb, vb, ob);
    // 7) out = ob @ Wo^T : [4096,2048]
    gemm_tc<<<dim3(DMODEL/128, MTOT/128, 1), blk, GEMM_SMEM_BYTES>>>(
        ob, Wo, out, MTOT, DMODEL, DMODEL, 0, 0, 0, 1);
}

// round 8
// speedup vs baseline: 3.9038x; 1.0069x over previous
#include <cuda_runtime.h>
#include <cstdint>
#include <math.h>

// ---------------- problem constants ----------------
#define BATCH 2
#define SEQ   2048
#define DMODEL 2048
#define NHEAD 16
#define HDIM  128
#define RQ    1536
#define RKV   512
#define MTOT  (BATCH*SEQ)          // 4096

// ---------------- scratch (allocation-free: __device__ globals) ----------------
__device__ float g_xq[(size_t)MTOT * RQ];            // X @ Wq_down^T
__device__ float g_q [(size_t)MTOT * DMODEL];        // Q  [B*L, H*d] (tf32-rounded)
__device__ float g_c [(size_t)MTOT * RKV];           // latent C
__device__ float g_k [(size_t)BATCH*NHEAD*SEQ*HDIM]; // K [B,H,L,d] (tf32-rounded)
__device__ float g_v [(size_t)BATCH*NHEAD*SEQ*HDIM]; // V [B,H,L,d] (tf32-rounded)
__device__ float g_o [(size_t)MTOT * DMODEL];        // attn out [B,L,H*d]
__device__ float g_kuT[(size_t)NHEAD*HDIM*RKV];      // k_up transposed: [H, d, r]
__device__ float g_vuT[(size_t)NHEAD*HDIM*RKV];      // v_up transposed

// ---------------- helpers ----------------
__device__ __forceinline__ uint32_t smem_u32(const void* p) {
    uint32_t a;
    asm("{ .reg .u64 t; cvta.to.shared.u64 t, %1; cvt.u32.u64 %0, t; }" : "=r"(a) : "l"(p));
    return a;
}
__device__ __forceinline__ uint32_t f2tf32(float x) {
    uint32_t r;
    asm("cvt.rna.tf32.f32 %0, %1;" : "=r"(r) : "f"(x));
    return r;
}
__device__ __forceinline__ uint32_t u2tf32(uint32_t bits) {
    uint32_t r;
    asm("cvt.rna.tf32.f32 %0, %1;" : "=r"(r) : "f"(__uint_as_float(bits)));
    return r;
}
__device__ __forceinline__ void cp16(uint32_t saddr, const void* gaddr) {
    asm volatile("cp.async.cg.shared.global [%0], [%1], 16;" :: "r"(saddr), "l"(gaddr));
}
#define CP_COMMIT()  asm volatile("cp.async.commit_group;" ::: "memory")
#define CP_WAIT_1()  asm volatile("cp.async.wait_group 1;" ::: "memory")
#define CP_WAIT_0()  asm volatile("cp.async.wait_group 0;" ::: "memory")

// mma.sync m16n8k8 tf32: D = A(16x8 row) * B(8x8 col) + C, fp32 accum.
__device__ __forceinline__ void mma_tf32(float& c0, float& c1, float& c2, float& c3,
                                         uint32_t a0, uint32_t a1, uint32_t a2, uint32_t a3,
                                         uint32_t b0, uint32_t b1) {
    asm volatile(
        "mma.sync.aligned.m16n8k8.row.col.f32.tf32.tf32.f32 "
        "{%0,%1,%2,%3}, {%4,%5,%6,%7}, {%8,%9}, {%0,%1,%2,%3};"
        : "+f"(c0), "+f"(c1), "+f"(c2), "+f"(c3)
        : "r"(a0), "r"(a1), "r"(a2), "r"(a3), "r"(b0), "r"(b1));
}

// ---------------- tf32 tensor-core GEMM: C = A @ B^T (cp.async double-buffered) ----------------
// A [M,K] row-major, B [N,K] row-major. M%128==0, N%128==0, K%32==0.
// RND: round outputs to tf32 values (for tensors consumed raw by flash mma).
#define BK 32
#define ST 36                       // row stride in words (32 + 4 pad)
#define GEMM_BUF_WORDS (128 * ST)   // 4608 words per tile buffer
#define GEMM_SMEM_BYTES (4 * GEMM_BUF_WORDS * 4)   // A0,B0,A1,B1 = 73728 B

template<bool RND>
__global__ __launch_bounds__(256)
void gemm_tc(const float* __restrict__ A, const float* __restrict__ B,
             float* __restrict__ C, int M, int N, int K,
             long sA, long sB, long sC, int hmod)
{
    extern __shared__ uint32_t sh[];
    const uint32_t sbase = smem_u32(sh);

    const int tid = threadIdx.x;
    const int wid = tid >> 5, lane = tid & 31;
    const int g = lane >> 2, t = lane & 3;           // groupID / threadID_in_group
    const int z = blockIdx.z;
    const float* Ab = A + (long)(z / hmod) * sA;
    const float* Bb = B + (long)(z % hmod) * sB;
    float* Cb = C + (long)z * sC;
    const int m0 = blockIdx.y * 128;
    const int n0 = blockIdx.x * 128;

    const int wm = (wid & 1) * 64;                   // warp tile origin in M
    const int wn = (wid >> 1) * 32;                  // warp tile origin in N

    float acc[4][4][4];
    #pragma unroll
    for (int m = 0; m < 4; m++)
        #pragma unroll
        for (int n = 0; n < 4; n++)
            #pragma unroll
            for (int r = 0; r < 4; r++) acc[m][n][r] = 0.f;

    const int lrow = tid >> 3;          // 0..31
    const int lc4  = (tid & 7) << 2;    // 0,4,..,28

    auto issue = [&](int k0, int b) {
        const uint32_t abase = sbase + (uint32_t)b * (2u * GEMM_BUF_WORDS * 4u);
        const uint32_t bbase = abase + GEMM_BUF_WORDS * 4u;
        #pragma unroll
        for (int p = 0; p < 4; p++) {
            const int row = lrow + p * 32;
            const uint32_t so = (uint32_t)(row * ST + lc4) * 4u;
            cp16(abase + so, Ab + (long)(m0 + row) * K + k0 + lc4);
            cp16(bbase + so, Bb + (long)(n0 + row) * K + k0 + lc4);
        }
        CP_COMMIT();
    };

    const int KT = K >> 5;
    issue(0, 0);

    for (int kt = 0; kt < KT; kt++) {
        if (kt + 1 < KT) { issue((kt + 1) << 5, (kt + 1) & 1); CP_WAIT_1(); }
        else             { CP_WAIT_0(); }
        __syncthreads();

        const uint32_t* Asb = sh + (size_t)(kt & 1) * (2 * GEMM_BUF_WORDS);
        const uint32_t* Bsb = Asb + GEMM_BUF_WORDS;

        #pragma unroll
        for (int ks = 0; ks < BK / 8; ks++) {
            const int kk = ks * 8;
            uint32_t af[4][4], bf[4][2];
            #pragma unroll
            for (int m = 0; m < 4; m++) {
                const int r0 = (wm + m * 16 + g) * ST + kk;
                const int r1 = (wm + m * 16 + g + 8) * ST + kk;
                af[m][0] = u2tf32(Asb[r0 + t]);
                af[m][1] = u2tf32(Asb[r1 + t]);
                af[m][2] = u2tf32(Asb[r0 + t + 4]);
                af[m][3] = u2tf32(Asb[r1 + t + 4]);
            }
            #pragma unroll
            for (int n = 0; n < 4; n++) {
                const int rn = (wn + n * 8 + g) * ST + kk;
                bf[n][0] = u2tf32(Bsb[rn + t]);
                bf[n][1] = u2tf32(Bsb[rn + t + 4]);
            }
            #pragma unroll
            for (int m = 0; m < 4; m++)
                #pragma unroll
                for (int n = 0; n < 4; n++)
                    mma_tf32(acc[m][n][0], acc[m][n][1], acc[m][n][2], acc[m][n][3],
                             af[m][0], af[m][1], af[m][2], af[m][3],
                             bf[n][0], bf[n][1]);
        }
        __syncthreads();
    }

    #pragma unroll
    for (int m = 0; m < 4; m++) {
        const long row0 = m0 + wm + m * 16 + g;
        #pragma unroll
        for (int n = 0; n < 4; n++) {
            const int col = n0 + wn + n * 8 + 2 * t;
            float v0 = acc[m][n][0], v1 = acc[m][n][1];
            float v2 = acc[m][n][2], v3 = acc[m][n][3];
            if (RND) {
                v0 = __uint_as_float(f2tf32(v0)); v1 = __uint_as_float(f2tf32(v1));
                v2 = __uint_as_float(f2tf32(v2)); v3 = __uint_as_float(f2tf32(v3));
            }
            *(float2*)(Cb + row0 * N + col)       = make_float2(v0, v1);
            *(float2*)(Cb + (row0 + 8) * N + col) = make_float2(v2, v3);
        }
    }
}

// ---------------- transpose [H, RKV, HDIM] -> [H, HDIM, RKV] ----------------
__global__ __launch_bounds__(256)
void transpose_up(const float* __restrict__ in, float* __restrict__ out)
{
    __shared__ float t[32][33];
    const int h = blockIdx.z;
    const int r0 = blockIdx.y * 32;   // RKV dim
    const int c0 = blockIdx.x * 32;   // HDIM dim
    const int tx = threadIdx.x & 31, ty0 = threadIdx.x >> 5;
    const float* ip = in + (long)h * RKV * HDIM;
    float* op = out + (long)h * RKV * HDIM;
    #pragma unroll
    for (int r = 0; r < 4; r++) {
        int ty = ty0 + r * 8;
        t[ty][tx] = ip[(long)(r0 + ty) * HDIM + c0 + tx];
    }
    __syncthreads();
    #pragma unroll
    for (int r = 0; r < 4; r++) {
        int ty = ty0 + r * 8;
        op[(long)(c0 + ty) * RKV + r0 + tx] = t[tx][ty];
    }
}

// ---------------- tensor-core flash attention (tf32 mma, ALiBi + causal) ----------------
// BM=64 q-rows/CTA, BN=64 kv per iter, d=128. 256 threads, 8 warps.
// Q/K/V are tf32-rounded by their producer GEMMs -> raw bits feed mma directly (no cvt).
// cp.async pipeline: Q+K0+V0 prefetched; each iter prefetches K/V(kt+1) into double buffers.
// Row softmax state combined across the two N-warps via smem (Red/Sum).
#define FQS 132                      // Q,K row stride (words): frag banks 4g+t, conflict-free
#define FVS 136                      // V row stride: frag banks 8t+g, conflict-free
#define FPS 68
#define F_KOFF   (64*FQS)
#define F_VOFF   (F_KOFF + 2*64*FQS)
#define F_POFF   (F_VOFF + 2*64*FVS)
#define F_ROFF   (F_POFF + 64*FPS)
#define FLASH_SMEM_WORDS (F_ROFF + 256)
#define FLASH_SMEM_BYTES (FLASH_SMEM_WORDS * 4)     // 189440 B

__global__ __launch_bounds__(256)
void flash_tc(const float* __restrict__ Q, const float* __restrict__ Kg,
              const float* __restrict__ Vg, float* __restrict__ O)
{
    extern __shared__ uint32_t sm[];
    const uint32_t sbase = smem_u32(sm);
    uint32_t* Qs = sm;                              // [64][132]
    uint32_t* Ps = sm + F_POFF;                     // [64][68] tf32
    float*    Red = (float*)(sm + F_ROFF);          // [2][64] partial max
    float*    Sum = Red + 128;                      // [2][64] partial sum

    const int bh = blockIdx.y;
    const int b  = bh >> 4, h = bh & 15;
    const int qt = blockIdx.x;
    const int q0 = qt * 64;
    const int tid = threadIdx.x;
    const int wid = tid >> 5, lane = tid & 31;
    const int g = lane >> 2, t = lane & 3;
    const int mw = wid & 3;                   // M strip (16 rows)
    const int nw = wid >> 2;                  // N strip

    const float slope = exp2f(-0.5f * (float)(h + 1));
    const float scale = 0.08838834764831843f;

    const float* Qbase = Q  + ((long)(b*SEQ + q0)) * DMODEL + h*HDIM;
    const float* Kbase = Kg + ((long)(b*NHEAD + h)) * SEQ * HDIM;
    const float* Vbase = Vg + ((long)(b*NHEAD + h)) * SEQ * HDIM;

    auto issueK = [&](int k0, int buf) {
        const uint32_t base = sbase + (uint32_t)(F_KOFF + buf * 64 * FQS) * 4u;
        #pragma unroll
        for (int p = 0; p < 8; p++) {
            int idx = tid + p*256;
            int row = idx >> 5, c4 = (idx & 31) << 2;
            cp16(base + (uint32_t)(row*FQS + c4)*4u, Kbase + (long)(k0+row)*HDIM + c4);
        }
    };
    auto issueV = [&](int k0, int buf) {
        const uint32_t base = sbase + (uint32_t)(F_VOFF + buf * 64 * FVS) * 4u;
        #pragma unroll
        for (int p = 0; p < 8; p++) {
            int idx = tid + p*256;
            int row = idx >> 5, c4 = (idx & 31) << 2;
            cp16(base + (uint32_t)(row*FVS + c4)*4u, Vbase + (long)(k0+row)*HDIM + c4);
        }
    };

    // prefetch group 0: Q tile + K0 + V0
    #pragma unroll
    for (int p = 0; p < 8; p++) {
        int idx = tid + p*256;
        int row = idx >> 5, c4 = (idx & 31) << 2;
        cp16(sbase + (uint32_t)(row*FQS + c4)*4u, Qbase + (long)row*DMODEL + c4);
    }
    issueK(0, 0); issueV(0, 0);
    CP_COMMIT();

    const int r0 = mw*16 + g, r1 = r0 + 8;    // this thread's q rows (local)
    const int qi0 = q0 + r0, qi1 = q0 + r1;

    float o[8][4];
    #pragma unroll
    for (int n = 0; n < 8; n++)
        #pragma unroll
        for (int r = 0; r < 4; r++) o[n][r] = 0.f;
    float m0 = -INFINITY, m1 = -INFINITY, l0 = 0.f, l1 = 0.f;

    for (int kt = 0; kt <= qt; kt++) {
        const int k0 = kt * 64;
        __syncthreads();   // (a) all warps done with prev iteration -> buf (kt+1)&1 free
        if (kt < qt) {
            issueK(k0 + 64, (kt + 1) & 1);
            issueV(k0 + 64, (kt + 1) & 1);
            CP_COMMIT();
            CP_WAIT_1();   // K(kt),V(kt) (+Q at kt=0) complete
        } else {
            CP_WAIT_0();
        }
        __syncthreads();   // (c) visibility of completed copies to all warps

        const uint32_t* Kb = sm + F_KOFF + (size_t)(kt & 1) * (64 * FQS);
        const uint32_t* Vb = sm + F_VOFF + (size_t)(kt & 1) * (64 * FVS);

        // S = Q @ K^T  (warp tile 16x32: 4 n-subtiles), raw tf32-valued bits
        float s[4][4];
        #pragma unroll
        for (int n = 0; n < 4; n++)
            #pragma unroll
            for (int r = 0; r < 4; r++) s[n][r] = 0.f;
        #pragma unroll
        for (int ks = 0; ks < 16; ks++) {
            const int kk = ks * 8;
            uint32_t a0 = Qs[r0*FQS + kk + t];
            uint32_t a1 = Qs[r1*FQS + kk + t];
            uint32_t a2 = Qs[r0*FQS + kk + t + 4];
            uint32_t a3 = Qs[r1*FQS + kk + t + 4];
            #pragma unroll
            for (int n = 0; n < 4; n++) {
                const int nr = nw*32 + n*8 + g;
                uint32_t b0 = Kb[nr*FQS + kk + t];
                uint32_t b1 = Kb[nr*FQS + kk + t + 4];
                mma_tf32(s[n][0], s[n][1], s[n][2], s[n][3], a0, a1, a2, a3, b0, b1);
            }
        }

        // scale + ALiBi + causal, partial (this warp's 32-col half) row max
        float rv0 = -INFINITY, rv1 = -INFINITY;
        #pragma unroll
        for (int n = 0; n < 4; n++) {
            const int kj = k0 + nw*32 + n*8 + 2*t;
            s[n][0] = (kj   <= qi0) ? fmaf(s[n][0], scale, -slope*(float)(qi0-kj))   : -INFINITY;
            s[n][1] = (kj+1 <= qi0) ? fmaf(s[n][1], scale, -slope*(float)(qi0-kj-1)) : -INFINITY;
            s[n][2] = (kj   <= qi1) ? fmaf(s[n][2], scale, -slope*(float)(qi1-kj))   : -INFINITY;
            s[n][3] = (kj+1 <= qi1) ? fmaf(s[n][3], scale, -slope*(float)(qi1-kj-1)) : -INFINITY;
            rv0 = fmaxf(rv0, fmaxf(s[n][0], s[n][1]));
            rv1 = fmaxf(rv1, fmaxf(s[n][2], s[n][3]));
        }
        rv0 = fmaxf(rv0, __shfl_xor_sync(0xffffffffu, rv0, 1));
        rv0 = fmaxf(rv0, __shfl_xor_sync(0xffffffffu, rv0, 2));
        rv1 = fmaxf(rv1, __shfl_xor_sync(0xffffffffu, rv1, 1));
        rv1 = fmaxf(rv1, __shfl_xor_sync(0xffffffffu, rv1, 2));
        if (t == 0) { Red[nw*64 + r0] = rv0; Red[nw*64 + r1] = rv1; }
        __syncthreads();   // (e) partial maxes visible

        // combined (full-row) max -> consistent softmax across both warp halves
        rv0 = fmaxf(Red[r0], Red[64 + r0]);
        rv1 = fmaxf(Red[r1], Red[64 + r1]);
        const float m0n = fmaxf(m0, rv0), m1n = fmaxf(m1, rv1);
        const float al0 = __expf(m0 - m0n), al1 = __expf(m1 - m1n);
        m0 = m0n; m1 = m1n;
        float rs0 = 0.f, rs1 = 0.f;
        #pragma unroll
        for (int n = 0; n < 4; n++) {
            float p00 = __expf(s[n][0] - m0n), p01 = __expf(s[n][1] - m0n);
            float p10 = __expf(s[n][2] - m1n), p11 = __expf(s[n][3] - m1n);
            rs0 += p00 + p01; rs1 += p10 + p11;
            const int cn = nw*32 + n*8 + 2*t;
            Ps[r0*FPS + cn] = f2tf32(p00); Ps[r0*FPS + cn + 1] = f2tf32(p01);
            Ps[r1*FPS + cn] = f2tf32(p10); Ps[r1*FPS + cn + 1] = f2tf32(p11);
        }
        rs0 += __shfl_xor_sync(0xffffffffu, rs0, 1);
        rs0 += __shfl_xor_sync(0xffffffffu, rs0, 2);
        rs1 += __shfl_xor_sync(0xffffffffu, rs1, 1);
        rs1 += __shfl_xor_sync(0xffffffffu, rs1, 2);
        if (t == 0) { Sum[nw*64 + r0] = rs0; Sum[nw*64 + r1] = rs1; }
        __syncthreads();   // (g) Ps + partial sums complete

        // combined row sum; update l and rescale o
        rs0 = Sum[r0] + Sum[64 + r0];
        rs1 = Sum[r1] + Sum[64 + r1];
        l0 = l0 * al0 + rs0; l1 = l1 * al1 + rs1;
        #pragma unroll
        for (int n = 0; n < 8; n++) {
            o[n][0] *= al0; o[n][1] *= al0; o[n][2] *= al1; o[n][3] *= al1;
        }

        // O += P @ V  (warp tile 16x64: 8 d-subtiles), raw V bits
        #pragma unroll
        for (int ks = 0; ks < 8; ks++) {
            const int kk = ks * 8;
            uint32_t a0 = Ps[r0*FPS + kk + t];
            uint32_t a1 = Ps[r1*FPS + kk + t];
            uint32_t a2 = Ps[r0*FPS + kk + t + 4];
            uint32_t a3 = Ps[r1*FPS + kk + t + 4];
            #pragma unroll
            for (int n = 0; n < 8; n++) {
                const int col = nw*64 + n*8 + g;
                uint32_t b0 = Vb[(kk + t)*FVS + col];
                uint32_t b1 = Vb[(kk + t + 4)*FVS + col];
                mma_tf32(o[n][0], o[n][1], o[n][2], o[n][3], a0, a1, a2, a3, b0, b1);
            }
        }
    }

    // normalize + write O[b, q, h*128 + col]
    const float inv0 = 1.f / l0, inv1 = 1.f / l1;
    const long row0 = (long)(b*SEQ + q0 + r0);
    const long row1 = (long)(b*SEQ + q0 + r1);
    #pragma unroll
    for (int n = 0; n < 8; n++) {
        const int col = h*HDIM + nw*64 + n*8 + 2*t;
        *(float2*)(O + row0*DMODEL + col) = make_float2(o[n][0]*inv0, o[n][1]*inv0);
        *(float2*)(O + row1*DMODEL + col) = make_float2(o[n][2]*inv1, o[n][3]*inv1);
    }
}

// ---------------- launch ----------------
extern "C" void kernel_launch(void* const* d_in, const int* in_sizes, int n_in,
                              void* d_out, int out_size)
{
    const float* X        = (const float*)d_in[0];
    const float* Wq_down  = (const float*)d_in[1];   // [1536, 2048]
    const float* Wq_up    = (const float*)d_in[2];   // [2048, 1536]
    const float* Wkv_down = (const float*)d_in[3];   // [512, 2048]
    const float* k_up     = (const float*)d_in[4];   // [16, 512, 128]
    const float* v_up     = (const float*)d_in[5];   // [16, 512, 128]
    const float* Wo       = (const float*)d_in[6];   // [2048, 2048]
    float* out = (float*)d_out;

    float *xq, *q, *c, *kb, *vb, *ob, *kuT, *vuT;
    cudaGetSymbolAddress((void**)&xq,  g_xq);
    cudaGetSymbolAddress((void**)&q,   g_q);
    cudaGetSymbolAddress((void**)&c,   g_c);
    cudaGetSymbolAddress((void**)&kb,  g_k);
    cudaGetSymbolAddress((void**)&vb,  g_v);
    cudaGetSymbolAddress((void**)&ob,  g_o);
    cudaGetSymbolAddress((void**)&kuT, g_kuT);
    cudaGetSymbolAddress((void**)&vuT, g_vuT);

    cudaFuncSetAttribute(gemm_tc<false>,
                         cudaFuncAttributeMaxDynamicSharedMemorySize, GEMM_SMEM_BYTES);
    cudaFuncSetAttribute(gemm_tc<true>,
                         cudaFuncAttributeMaxDynamicSharedMemorySize, GEMM_SMEM_BYTES);
    cudaFuncSetAttribute(flash_tc,
                         cudaFuncAttributeMaxDynamicSharedMemorySize, FLASH_SMEM_BYTES);

    dim3 blk(256);

    // 0) transpose k_up/v_up -> [H, HDIM, RKV] so all GEMMs consume K-major B
    transpose_up<<<dim3(HDIM/32, RKV/32, NHEAD), blk>>>(k_up, kuT);
    transpose_up<<<dim3(HDIM/32, RKV/32, NHEAD), blk>>>(v_up, vuT);

    // 1) Xq = X @ Wq_down^T : [4096,1536]
    gemm_tc<false><<<dim3(RQ/128, MTOT/128, 1), blk, GEMM_SMEM_BYTES>>>(
        X, Wq_down, xq, MTOT, RQ, DMODEL, 0, 0, 0, 1);
    // 2) Q = Xq @ Wq_up^T : [4096,2048]  (tf32-rounded for flash)
    gemm_tc<true><<<dim3(DMODEL/128, MTOT/128, 1), blk, GEMM_SMEM_BYTES>>>(
        xq, Wq_up, q, MTOT, DMODEL, RQ, 0, 0, 0, 1);
    // 3) C = X @ Wkv_down^T : [4096,512]
    gemm_tc<false><<<dim3(RKV/128, MTOT/128, 1), blk, GEMM_SMEM_BYTES>>>(
        X, Wkv_down, c, MTOT, RKV, DMODEL, 0, 0, 0, 1);
    // 4) K[b,h] = C_b @ kuT[h]^T : batched 32x [2048,128]  (tf32-rounded)
    gemm_tc<true><<<dim3(1, SEQ/128, BATCH*NHEAD), blk, GEMM_SMEM_BYTES>>>(
        c, kuT, kb, SEQ, HDIM, RKV,
        (long)SEQ*RKV, (long)HDIM*RKV, (long)SEQ*HDIM, NHEAD);
    // 5) V likewise (tf32-rounded)
    gemm_tc<true><<<dim3(1, SEQ/128, BATCH*NHEAD), blk, GEMM_SMEM_BYTES>>>(
        c, vuT, vb, SEQ, HDIM, RKV,
        (long)SEQ*RKV, (long)HDIM*RKV, (long)SEQ*HDIM, NHEAD);
    // 6) tensor-core causal+ALiBi flash attention -> ob [B,L,H*d]
    flash_tc<<<dim3(SEQ/64, BATCH*NHEAD), blk, FLASH_SMEM_BYTES>>>(q, kb, vb, ob);
    // 7) out = ob @ Wo^T : [4096,2048]
    gemm_tc<false><<<dim3(DMODEL/128, MTOT/128, 1), blk, GEMM_SMEM_BYTES>>>(
        ob, Wo, out, MTOT, DMODEL, DMODEL, 0, 0, 0, 1);
}

// round 9
// speedup vs baseline: 4.0894x; 1.0476x over previous
#include <cuda_runtime.h>
#include <cstdint>
#include <math.h>

// ---------------- problem constants ----------------
#define BATCH 2
#define SEQ   2048
#define DMODEL 2048
#define NHEAD 16
#define HDIM  128
#define RQ    1536
#define RKV   512
#define MTOT  (BATCH*SEQ)          // 4096

// ---------------- scratch (allocation-free: __device__ globals) ----------------
__device__ float g_xq[(size_t)MTOT * RQ];            // X @ Wq_down^T (tf32-rounded)
__device__ float g_q [(size_t)MTOT * DMODEL];        // Q (tf32-rounded)
__device__ float g_c [(size_t)MTOT * RKV];           // latent C (tf32-rounded)
__device__ float g_k [(size_t)BATCH*NHEAD*SEQ*HDIM]; // K (tf32-rounded)
__device__ float g_v [(size_t)BATCH*NHEAD*SEQ*HDIM]; // V (tf32-rounded)
__device__ float g_o [(size_t)MTOT * DMODEL];        // attn out (tf32-rounded)
__device__ float g_kuT[(size_t)NHEAD*HDIM*RKV];      // k_up^T (tf32-rounded)
__device__ float g_vuT[(size_t)NHEAD*HDIM*RKV];      // v_up^T (tf32-rounded)
// tf32-rounded copies of raw inputs
__device__ float g_xr  [(size_t)MTOT * DMODEL];
__device__ float g_wqdr[(size_t)RQ * DMODEL];
__device__ float g_wqur[(size_t)DMODEL * RQ];
__device__ float g_wkdr[(size_t)RKV * DMODEL];
__device__ float g_wor [(size_t)DMODEL * DMODEL];

// ---------------- helpers ----------------
__device__ __forceinline__ uint32_t smem_u32(const void* p) {
    uint32_t a;
    asm("{ .reg .u64 t; cvta.to.shared.u64 t, %1; cvt.u32.u64 %0, t; }" : "=r"(a) : "l"(p));
    return a;
}
__device__ __forceinline__ uint32_t f2tf32(float x) {
    uint32_t r;
    asm("cvt.rna.tf32.f32 %0, %1;" : "=r"(r) : "f"(x));
    return r;
}
__device__ __forceinline__ float f2tf32f(float x) { return __uint_as_float(f2tf32(x)); }
__device__ __forceinline__ void cp16(uint32_t saddr, const void* gaddr) {
    asm volatile("cp.async.cg.shared.global [%0], [%1], 16;" :: "r"(saddr), "l"(gaddr));
}
#define CP_COMMIT()  asm volatile("cp.async.commit_group;" ::: "memory")
#define CP_WAIT_1()  asm volatile("cp.async.wait_group 1;" ::: "memory")
#define CP_WAIT_0()  asm volatile("cp.async.wait_group 0;" ::: "memory")

// mma.sync m16n8k8 tf32: D = A(16x8 row) * B(8x8 col) + C, fp32 accum.
__device__ __forceinline__ void mma_tf32(float& c0, float& c1, float& c2, float& c3,
                                         uint32_t a0, uint32_t a1, uint32_t a2, uint32_t a3,
                                         uint32_t b0, uint32_t b1) {
    asm volatile(
        "mma.sync.aligned.m16n8k8.row.col.f32.tf32.tf32.f32 "
        "{%0,%1,%2,%3}, {%4,%5,%6,%7}, {%8,%9}, {%0,%1,%2,%3};"
        : "+f"(c0), "+f"(c1), "+f"(c2), "+f"(c3)
        : "r"(a0), "r"(a1), "r"(a2), "r"(a3), "r"(b0), "r"(b1));
}

// ---------------- elementwise tf32 rounding copy ----------------
__global__ __launch_bounds__(256)
void round_tf32(const float* __restrict__ in, float* __restrict__ out, long n4)
{
    long i = (long)blockIdx.x * blockDim.x + threadIdx.x;
    long stride = (long)gridDim.x * blockDim.x;
    for (; i < n4; i += stride) {
        float4 v = ((const float4*)in)[i];
        v.x = f2tf32f(v.x); v.y = f2tf32f(v.y); v.z = f2tf32f(v.z); v.w = f2tf32f(v.w);
        ((float4*)out)[i] = v;
    }
}

// ---------------- tf32 tensor-core GEMM: C = A @ B^T (cp.async double-buffered) ----------------
// ALL inputs must be tf32-valued fp32 in gmem (pre-rounded) -> no cvt in mainloop.
// A [M,K] row-major, B [N,K] row-major. M%128==0, N%128==0, K%32==0.
// RND: round outputs to tf32 (for tensors consumed by later mma stages).
#define BK 32
#define ST 36                       // row stride in words (32 + 4 pad)
#define GEMM_BUF_WORDS (128 * ST)   // 4608 words per tile buffer
#define GEMM_SMEM_BYTES (4 * GEMM_BUF_WORDS * 4)   // A0,B0,A1,B1 = 73728 B

template<bool RND>
__global__ __launch_bounds__(256, 2)
void gemm_tc(const float* __restrict__ A, const float* __restrict__ B,
             float* __restrict__ C, int M, int N, int K,
             long sA, long sB, long sC, int hmod)
{
    extern __shared__ uint32_t sh[];
    const uint32_t sbase = smem_u32(sh);

    const int tid = threadIdx.x;
    const int wid = tid >> 5, lane = tid & 31;
    const int g = lane >> 2, t = lane & 3;           // groupID / threadID_in_group
    const int z = blockIdx.z;
    const float* Ab = A + (long)(z / hmod) * sA;
    const float* Bb = B + (long)(z % hmod) * sB;
    float* Cb = C + (long)z * sC;
    const int m0 = blockIdx.y * 128;
    const int n0 = blockIdx.x * 128;

    const int wm = (wid & 1) * 64;                   // warp tile origin in M
    const int wn = (wid >> 1) * 32;                  // warp tile origin in N

    float acc[4][4][4];
    #pragma unroll
    for (int m = 0; m < 4; m++)
        #pragma unroll
        for (int n = 0; n < 4; n++)
            #pragma unroll
            for (int r = 0; r < 4; r++) acc[m][n][r] = 0.f;

    const int lrow = tid >> 3;          // 0..31
    const int lc4  = (tid & 7) << 2;    // 0,4,..,28

    auto issue = [&](int k0, int b) {
        const uint32_t abase = sbase + (uint32_t)b * (2u * GEMM_BUF_WORDS * 4u);
        const uint32_t bbase = abase + GEMM_BUF_WORDS * 4u;
        #pragma unroll
        for (int p = 0; p < 4; p++) {
            const int row = lrow + p * 32;
            const uint32_t so = (uint32_t)(row * ST + lc4) * 4u;
            cp16(abase + so, Ab + (long)(m0 + row) * K + k0 + lc4);
            cp16(bbase + so, Bb + (long)(n0 + row) * K + k0 + lc4);
        }
        CP_COMMIT();
    };

    const int KT = K >> 5;
    issue(0, 0);

    for (int kt = 0; kt < KT; kt++) {
        if (kt + 1 < KT) { issue((kt + 1) << 5, (kt + 1) & 1); CP_WAIT_1(); }
        else             { CP_WAIT_0(); }
        __syncthreads();

        const uint32_t* Asb = sh + (size_t)(kt & 1) * (2 * GEMM_BUF_WORDS);
        const uint32_t* Bsb = Asb + GEMM_BUF_WORDS;

        #pragma unroll
        for (int ks = 0; ks < BK / 8; ks++) {
            const int kk = ks * 8;
            uint32_t af[4][4], bf[4][2];
            #pragma unroll
            for (int m = 0; m < 4; m++) {
                const int r0 = (wm + m * 16 + g) * ST + kk;
                const int r1 = (wm + m * 16 + g + 8) * ST + kk;
                af[m][0] = Asb[r0 + t];
                af[m][1] = Asb[r1 + t];
                af[m][2] = Asb[r0 + t + 4];
                af[m][3] = Asb[r1 + t + 4];
            }
            #pragma unroll
            for (int n = 0; n < 4; n++) {
                const int rn = (wn + n * 8 + g) * ST + kk;
                bf[n][0] = Bsb[rn + t];
                bf[n][1] = Bsb[rn + t + 4];
            }
            #pragma unroll
            for (int m = 0; m < 4; m++)
                #pragma unroll
                for (int n = 0; n < 4; n++)
                    mma_tf32(acc[m][n][0], acc[m][n][1], acc[m][n][2], acc[m][n][3],
                             af[m][0], af[m][1], af[m][2], af[m][3],
                             bf[n][0], bf[n][1]);
        }
        __syncthreads();
    }

    #pragma unroll
    for (int m = 0; m < 4; m++) {
        const long row0 = m0 + wm + m * 16 + g;
        #pragma unroll
        for (int n = 0; n < 4; n++) {
            const int col = n0 + wn + n * 8 + 2 * t;
            float v0 = acc[m][n][0], v1 = acc[m][n][1];
            float v2 = acc[m][n][2], v3 = acc[m][n][3];
            if (RND) {
                v0 = f2tf32f(v0); v1 = f2tf32f(v1);
                v2 = f2tf32f(v2); v3 = f2tf32f(v3);
            }
            *(float2*)(Cb + row0 * N + col)       = make_float2(v0, v1);
            *(float2*)(Cb + (row0 + 8) * N + col) = make_float2(v2, v3);
        }
    }
}

// ---------------- transpose [H, RKV, HDIM] -> [H, HDIM, RKV], tf32-round on store ----------------
__global__ __launch_bounds__(256)
void transpose_up(const float* __restrict__ in, float* __restrict__ out)
{
    __shared__ float t[32][33];
    const int h = blockIdx.z;
    const int r0 = blockIdx.y * 32;   // RKV dim
    const int c0 = blockIdx.x * 32;   // HDIM dim
    const int tx = threadIdx.x & 31, ty0 = threadIdx.x >> 5;
    const float* ip = in + (long)h * RKV * HDIM;
    float* op = out + (long)h * RKV * HDIM;
    #pragma unroll
    for (int r = 0; r < 4; r++) {
        int ty = ty0 + r * 8;
        t[ty][tx] = ip[(long)(r0 + ty) * HDIM + c0 + tx];
    }
    __syncthreads();
    #pragma unroll
    for (int r = 0; r < 4; r++) {
        int ty = ty0 + r * 8;
        op[(long)(c0 + ty) * RKV + r0 + tx] = f2tf32f(t[tx][ty]);
    }
}

// ---------------- tensor-core flash attention (tf32 mma, ALiBi + causal) ----------------
// BM=64 q-rows/CTA, BN=64 kv per iter, d=128. 256 threads, 8 warps.
// Q/K/V tf32-rounded by producers -> raw bits feed mma directly.
// cp.async double-buffered K/V pipeline; cross-warp row softmax via smem Red/Sum.
// Output rounded to tf32 on store (consumed by the Wo GEMM's raw fragment path).
#define FQS 132
#define FVS 136
#define FPS 68
#define F_KOFF   (64*FQS)
#define F_VOFF   (F_KOFF + 2*64*FQS)
#define F_POFF   (F_VOFF + 2*64*FVS)
#define F_ROFF   (F_POFF + 64*FPS)
#define FLASH_SMEM_WORDS (F_ROFF + 256)
#define FLASH_SMEM_BYTES (FLASH_SMEM_WORDS * 4)     // 189440 B

__global__ __launch_bounds__(256)
void flash_tc(const float* __restrict__ Q, const float* __restrict__ Kg,
              const float* __restrict__ Vg, float* __restrict__ O)
{
    extern __shared__ uint32_t sm[];
    const uint32_t sbase = smem_u32(sm);
    uint32_t* Qs = sm;                              // [64][132]
    uint32_t* Ps = sm + F_POFF;                     // [64][68] tf32
    float*    Red = (float*)(sm + F_ROFF);          // [2][64] partial max
    float*    Sum = Red + 128;                      // [2][64] partial sum

    const int bh = blockIdx.y;
    const int b  = bh >> 4, h = bh & 15;
    const int qt = blockIdx.x;
    const int q0 = qt * 64;
    const int tid = threadIdx.x;
    const int wid = tid >> 5, lane = tid & 31;
    const int g = lane >> 2, t = lane & 3;
    const int mw = wid & 3;                   // M strip (16 rows)
    const int nw = wid >> 2;                  // N strip

    const float slope = exp2f(-0.5f * (float)(h + 1));
    const float scale = 0.08838834764831843f;

    const float* Qbase = Q  + ((long)(b*SEQ + q0)) * DMODEL + h*HDIM;
    const float* Kbase = Kg + ((long)(b*NHEAD + h)) * SEQ * HDIM;
    const float* Vbase = Vg + ((long)(b*NHEAD + h)) * SEQ * HDIM;

    auto issueK = [&](int k0, int buf) {
        const uint32_t base = sbase + (uint32_t)(F_KOFF + buf * 64 * FQS) * 4u;
        #pragma unroll
        for (int p = 0; p < 8; p++) {
            int idx = tid + p*256;
            int row = idx >> 5, c4 = (idx & 31) << 2;
            cp16(base + (uint32_t)(row*FQS + c4)*4u, Kbase + (long)(k0+row)*HDIM + c4);
        }
    };
    auto issueV = [&](int k0, int buf) {
        const uint32_t base = sbase + (uint32_t)(F_VOFF + buf * 64 * FVS) * 4u;
        #pragma unroll
        for (int p = 0; p < 8; p++) {
            int idx = tid + p*256;
            int row = idx >> 5, c4 = (idx & 31) << 2;
            cp16(base + (uint32_t)(row*FVS + c4)*4u, Vbase + (long)(k0+row)*HDIM + c4);
        }
    };

    // prefetch group 0: Q tile + K0 + V0
    #pragma unroll
    for (int p = 0; p < 8; p++) {
        int idx = tid + p*256;
        int row = idx >> 5, c4 = (idx & 31) << 2;
        cp16(sbase + (uint32_t)(row*FQS + c4)*4u, Qbase + (long)row*DMODEL + c4);
    }
    issueK(0, 0); issueV(0, 0);
    CP_COMMIT();

    const int r0 = mw*16 + g, r1 = r0 + 8;    // this thread's q rows (local)
    const int qi0 = q0 + r0, qi1 = q0 + r1;

    float o[8][4];
    #pragma unroll
    for (int n = 0; n < 8; n++)
        #pragma unroll
        for (int r = 0; r < 4; r++) o[n][r] = 0.f;
    float m0 = -INFINITY, m1 = -INFINITY, l0 = 0.f, l1 = 0.f;

    for (int kt = 0; kt <= qt; kt++) {
        const int k0 = kt * 64;
        __syncthreads();   // (a) all warps done with prev iteration -> buf (kt+1)&1 free
        if (kt < qt) {
            issueK(k0 + 64, (kt + 1) & 1);
            issueV(k0 + 64, (kt + 1) & 1);
            CP_COMMIT();
            CP_WAIT_1();   // K(kt),V(kt) (+Q at kt=0) complete
        } else {
            CP_WAIT_0();
        }
        __syncthreads();   // (c) visibility of completed copies to all warps

        const uint32_t* Kb = sm + F_KOFF + (size_t)(kt & 1) * (64 * FQS);
        const uint32_t* Vb = sm + F_VOFF + (size_t)(kt & 1) * (64 * FVS);

        // S = Q @ K^T  (warp tile 16x32: 4 n-subtiles), raw tf32-valued bits
        float s[4][4];
        #pragma unroll
        for (int n = 0; n < 4; n++)
            #pragma unroll
            for (int r = 0; r < 4; r++) s[n][r] = 0.f;
        #pragma unroll
        for (int ks = 0; ks < 16; ks++) {
            const int kk = ks * 8;
            uint32_t a0 = Qs[r0*FQS + kk + t];
            uint32_t a1 = Qs[r1*FQS + kk + t];
            uint32_t a2 = Qs[r0*FQS + kk + t + 4];
            uint32_t a3 = Qs[r1*FQS + kk + t + 4];
            #pragma unroll
            for (int n = 0; n < 4; n++) {
                const int nr = nw*32 + n*8 + g;
                uint32_t b0 = Kb[nr*FQS + kk + t];
                uint32_t b1 = Kb[nr*FQS + kk + t + 4];
                mma_tf32(s[n][0], s[n][1], s[n][2], s[n][3], a0, a1, a2, a3, b0, b1);
            }
        }

        // scale + ALiBi + causal, partial (this warp's 32-col half) row max
        float rv0 = -INFINITY, rv1 = -INFINITY;
        #pragma unroll
        for (int n = 0; n < 4; n++) {
            const int kj = k0 + nw*32 + n*8 + 2*t;
            s[n][0] = (kj   <= qi0) ? fmaf(s[n][0], scale, -slope*(float)(qi0-kj))   : -INFINITY;
            s[n][1] = (kj+1 <= qi0) ? fmaf(s[n][1], scale, -slope*(float)(qi0-kj-1)) : -INFINITY;
            s[n][2] = (kj   <= qi1) ? fmaf(s[n][2], scale, -slope*(float)(qi1-kj))   : -INFINITY;
            s[n][3] = (kj+1 <= qi1) ? fmaf(s[n][3], scale, -slope*(float)(qi1-kj-1)) : -INFINITY;
            rv0 = fmaxf(rv0, fmaxf(s[n][0], s[n][1]));
            rv1 = fmaxf(rv1, fmaxf(s[n][2], s[n][3]));
        }
        rv0 = fmaxf(rv0, __shfl_xor_sync(0xffffffffu, rv0, 1));
        rv0 = fmaxf(rv0, __shfl_xor_sync(0xffffffffu, rv0, 2));
        rv1 = fmaxf(rv1, __shfl_xor_sync(0xffffffffu, rv1, 1));
        rv1 = fmaxf(rv1, __shfl_xor_sync(0xffffffffu, rv1, 2));
        if (t == 0) { Red[nw*64 + r0] = rv0; Red[nw*64 + r1] = rv1; }
        __syncthreads();   // (e) partial maxes visible

        // combined (full-row) max -> consistent softmax across both warp halves
        rv0 = fmaxf(Red[r0], Red[64 + r0]);
        rv1 = fmaxf(Red[r1], Red[64 + r1]);
        const float m0n = fmaxf(m0, rv0), m1n = fmaxf(m1, rv1);
        const float al0 = __expf(m0 - m0n), al1 = __expf(m1 - m1n);
        m0 = m0n; m1 = m1n;
        float rs0 = 0.f, rs1 = 0.f;
        #pragma unroll
        for (int n = 0; n < 4; n++) {
            float p00 = __expf(s[n][0] - m0n), p01 = __expf(s[n][1] - m0n);
            float p10 = __expf(s[n][2] - m1n), p11 = __expf(s[n][3] - m1n);
            rs0 += p00 + p01; rs1 += p10 + p11;
            const int cn = nw*32 + n*8 + 2*t;
            Ps[r0*FPS + cn] = f2tf32(p00); Ps[r0*FPS + cn + 1] = f2tf32(p01);
            Ps[r1*FPS + cn] = f2tf32(p10); Ps[r1*FPS + cn + 1] = f2tf32(p11);
        }
        rs0 += __shfl_xor_sync(0xffffffffu, rs0, 1);
        rs0 += __shfl_xor_sync(0xffffffffu, rs0, 2);
        rs1 += __shfl_xor_sync(0xffffffffu, rs1, 1);
        rs1 += __shfl_xor_sync(0xffffffffu, rs1, 2);
        if (t == 0) { Sum[nw*64 + r0] = rs0; Sum[nw*64 + r1] = rs1; }
        __syncthreads();   // (g) Ps + partial sums complete

        // combined row sum; update l and rescale o
        rs0 = Sum[r0] + Sum[64 + r0];
        rs1 = Sum[r1] + Sum[64 + r1];
        l0 = l0 * al0 + rs0; l1 = l1 * al1 + rs1;
        #pragma unroll
        for (int n = 0; n < 8; n++) {
            o[n][0] *= al0; o[n][1] *= al0; o[n][2] *= al1; o[n][3] *= al1;
        }

        // O += P @ V  (warp tile 16x64: 8 d-subtiles), raw V bits
        #pragma unroll
        for (int ks = 0; ks < 8; ks++) {
            const int kk = ks * 8;
            uint32_t a0 = Ps[r0*FPS + kk + t];
            uint32_t a1 = Ps[r1*FPS + kk + t];
            uint32_t a2 = Ps[r0*FPS + kk + t + 4];
            uint32_t a3 = Ps[r1*FPS + kk + t + 4];
            #pragma unroll
            for (int n = 0; n < 8; n++) {
                const int col = nw*64 + n*8 + g;
                uint32_t b0 = Vb[(kk + t)*FVS + col];
                uint32_t b1 = Vb[(kk + t + 4)*FVS + col];
                mma_tf32(o[n][0], o[n][1], o[n][2], o[n][3], a0, a1, a2, a3, b0, b1);
            }
        }
    }

    // normalize + tf32-round + write O[b, q, h*128 + col]
    const float inv0 = 1.f / l0, inv1 = 1.f / l1;
    const long row0 = (long)(b*SEQ + q0 + r0);
    const long row1 = (long)(b*SEQ + q0 + r1);
    #pragma unroll
    for (int n = 0; n < 8; n++) {
        const int col = h*HDIM + nw*64 + n*8 + 2*t;
        *(float2*)(O + row0*DMODEL + col) = make_float2(f2tf32f(o[n][0]*inv0), f2tf32f(o[n][1]*inv0));
        *(float2*)(O + row1*DMODEL + col) = make_float2(f2tf32f(o[n][2]*inv1), f2tf32f(o[n][3]*inv1));
    }
}

// ---------------- launch ----------------
extern "C" void kernel_launch(void* const* d_in, const int* in_sizes, int n_in,
                              void* d_out, int out_size)
{
    const float* X        = (const float*)d_in[0];
    const float* Wq_down  = (const float*)d_in[1];   // [1536, 2048]
    const float* Wq_up    = (const float*)d_in[2];   // [2048, 1536]
    const float* Wkv_down = (const float*)d_in[3];   // [512, 2048]
    const float* k_up     = (const float*)d_in[4];   // [16, 512, 128]
    const float* v_up     = (const float*)d_in[5];   // [16, 512, 128]
    const float* Wo       = (const float*)d_in[6];   // [2048, 2048]
    float* out = (float*)d_out;

    float *xq, *q, *c, *kb, *vb, *ob, *kuT, *vuT;
    float *xr, *wqdr, *wqur, *wkdr, *wor;
    cudaGetSymbolAddress((void**)&xq,  g_xq);
    cudaGetSymbolAddress((void**)&q,   g_q);
    cudaGetSymbolAddress((void**)&c,   g_c);
    cudaGetSymbolAddress((void**)&kb,  g_k);
    cudaGetSymbolAddress((void**)&vb,  g_v);
    cudaGetSymbolAddress((void**)&ob,  g_o);
    cudaGetSymbolAddress((void**)&kuT, g_kuT);
    cudaGetSymbolAddress((void**)&vuT, g_vuT);
    cudaGetSymbolAddress((void**)&xr,   g_xr);
    cudaGetSymbolAddress((void**)&wqdr, g_wqdr);
    cudaGetSymbolAddress((void**)&wqur, g_wqur);
    cudaGetSymbolAddress((void**)&wkdr, g_wkdr);
    cudaGetSymbolAddress((void**)&wor,  g_wor);

    cudaFuncSetAttribute(gemm_tc<false>,
                         cudaFuncAttributeMaxDynamicSharedMemorySize, GEMM_SMEM_BYTES);
    cudaFuncSetAttribute(gemm_tc<true>,
                         cudaFuncAttributeMaxDynamicSharedMemorySize, GEMM_SMEM_BYTES);
    cudaFuncSetAttribute(gemm_tc<false>,
                         cudaFuncAttributePreferredSharedMemoryCarveout, 100);
    cudaFuncSetAttribute(gemm_tc<true>,
                         cudaFuncAttributePreferredSharedMemoryCarveout, 100);
    cudaFuncSetAttribute(flash_tc,
                         cudaFuncAttributeMaxDynamicSharedMemorySize, FLASH_SMEM_BYTES);

    dim3 blk(256);

    // 0) tf32-round all raw GEMM inputs (one-time copies)
    round_tf32<<<512, blk>>>(X,        xr,   (long)MTOT*DMODEL/4);
    round_tf32<<<512, blk>>>(Wq_down,  wqdr, (long)RQ*DMODEL/4);
    round_tf32<<<512, blk>>>(Wq_up,    wqur, (long)DMODEL*RQ/4);
    round_tf32<<<512, blk>>>(Wkv_down, wkdr, (long)RKV*DMODEL/4);
    round_tf32<<<512, blk>>>(Wo,       wor,  (long)DMODEL*DMODEL/4);
    transpose_up<<<dim3(HDIM/32, RKV/32, NHEAD), blk>>>(k_up, kuT);
    transpose_up<<<dim3(HDIM/32, RKV/32, NHEAD), blk>>>(v_up, vuT);

    // 1) Xq = X @ Wq_down^T : [4096,1536]  (rounded: feeds GEMM 2)
    gemm_tc<true><<<dim3(RQ/128, MTOT/128, 1), blk, GEMM_SMEM_BYTES>>>(
        xr, wqdr, xq, MTOT, RQ, DMODEL, 0, 0, 0, 1);
    // 2) Q = Xq @ Wq_up^T : [4096,2048]  (rounded: feeds flash)
    gemm_tc<true><<<dim3(DMODEL/128, MTOT/128, 1), blk, GEMM_SMEM_BYTES>>>(
        xq, wqur, q, MTOT, DMODEL, RQ, 0, 0, 0, 1);
    // 3) C = X @ Wkv_down^T : [4096,512]  (rounded: feeds GEMMs 4,5)
    gemm_tc<true><<<dim3(RKV/128, MTOT/128, 1), blk, GEMM_SMEM_BYTES>>>(
        xr, wkdr, c, MTOT, RKV, DMODEL, 0, 0, 0, 1);
    // 4) K[b,h] = C_b @ kuT[h]^T : batched 32x [2048,128]  (rounded)
    gemm_tc<true><<<dim3(1, SEQ/128, BATCH*NHEAD), blk, GEMM_SMEM_BYTES>>>(
        c, kuT, kb, SEQ, HDIM, RKV,
        (long)SEQ*RKV, (long)HDIM*RKV, (long)SEQ*HDIM, NHEAD);
    // 5) V likewise (rounded)
    gemm_tc<true><<<dim3(1, SEQ/128, BATCH*NHEAD), blk, GEMM_SMEM_BYTES>>>(
        c, vuT, vb, SEQ, HDIM, RKV,
        (long)SEQ*RKV, (long)HDIM*RKV, (long)SEQ*HDIM, NHEAD);
    // 6) tensor-core causal+ALiBi flash attention -> ob (rounded on store)
    flash_tc<<<dim3(SEQ/64, BATCH*NHEAD), blk, FLASH_SMEM_BYTES>>>(q, kb, vb, ob);
    // 7) out = ob @ Wo^T : [4096,2048]  (NOT rounded: final output)
    gemm_tc<false><<<dim3(DMODEL/128, MTOT/128, 1), blk, GEMM_SMEM_BYTES>>>(
        ob, wor, out, MTOT, DMODEL, DMODEL, 0, 0, 0, 1);
}